// round 1
// baseline (speedup 1.0000x reference)
#include <cuda_runtime.h>
#include <math.h>

// ---------------- problem constants ----------------
#define NB   128     // batch
#define TT   100     // time steps
#define SS   128     // state dim
#define AAd  32      // action dim
#define LL   1024    // enc hidden
#define ZZ   1024    // latent / dec hidden
#define GG   3072    // 3*hidden (gates)
#define TENC 98      // max encoder steps needed (end <= 97 since lengths <= 98)
#define TDEC 49      // max decoder steps needed (99 - min_length = 99-50)
#define MDEC (TDEC*NB)
#define KSPL 8       // k-split for recurrent step GEMMs

// ---------------- device scratch (no cudaMalloc allowed) ----------------
__device__ float g_xbuf  [TENC*NB*160];
__device__ float g_xg_enc[TENC*(size_t)NB*GG];
__device__ float g_abuf  [TDEC*NB*AAd];
__device__ float g_xg_dec[TDEC*(size_t)NB*GG];
__device__ float g_h     [NB*LL];
__device__ float g_hf    [NB*LL];
__device__ float g_gparts[KSPL*(size_t)NB*GG];
__device__ float g_muparts[4*NB*ZZ];
__device__ float g_lvparts[4*NB*ZZ];
__device__ float g_emb   [NB*ZZ];
__device__ float g_decout[TDEC*(size_t)NB*ZZ];
__device__ float g_y1    [MDEC*128];
__device__ float g_y2    [MDEC*64];
__device__ float g_shat  [MDEC*128];
__device__ float g_part  [MDEC];
__device__ int   g_end   [NB];
__device__ int   g_start [NB];

// ---------------- generic TN GEMM: C[m,n] = sum_k A[m,k]*B[n,k] ----------------
// grid.x = N/BN tiles, grid.y = M/BM tiles, grid.z = k-split (each handles klen of K)
// C laid out as [z][M][N]. All dims assumed exact multiples (holds for all calls).
#define BM 128
#define BN 64
#define BK 16
#define TM 8
#define TN 4

__global__ __launch_bounds__(256)
void gemm_tn(const float* __restrict__ A, const float* __restrict__ B,
             float* __restrict__ C, int M, int N, int K,
             int lda, int ldb, int klen)
{
    __shared__ float As[BK][BM+1];
    __shared__ float Bs[BK][BN+1];
    int tid = threadIdx.x;
    int m0 = blockIdx.y * BM;
    int n0 = blockIdx.x * BN;
    int k0 = blockIdx.z * klen;
    int kend = k0 + klen; if (kend > K) kend = K;
    int tx = tid & 15, ty = tid >> 4;

    float acc[TM][TN];
    #pragma unroll
    for (int i = 0; i < TM; i++)
        #pragma unroll
        for (int j = 0; j < TN; j++) acc[i][j] = 0.f;

    for (int kb = k0; kb < kend; kb += BK) {
        #pragma unroll
        for (int r = 0; r < (BK*BM)/256; r++) {
            int e = r*256 + tid;
            int kk = e & (BK-1);
            int mm = e >> 4;
            As[kk][mm] = A[(size_t)(m0+mm)*lda + kb + kk];
        }
        #pragma unroll
        for (int r = 0; r < (BK*BN)/256; r++) {
            int e = r*256 + tid;
            int kk = e & (BK-1);
            int nn = e >> 4;
            Bs[kk][nn] = B[(size_t)(n0+nn)*ldb + kb + kk];
        }
        __syncthreads();
        #pragma unroll
        for (int kk = 0; kk < BK; kk++) {
            float ra[TM], rb[TN];
            #pragma unroll
            for (int i = 0; i < TM; i++) ra[i] = As[kk][ty*TM+i];
            #pragma unroll
            for (int j = 0; j < TN; j++) rb[j] = Bs[kk][tx*TN+j];
            #pragma unroll
            for (int i = 0; i < TM; i++)
                #pragma unroll
                for (int j = 0; j < TN; j++)
                    acc[i][j] = fmaf(ra[i], rb[j], acc[i][j]);
        }
        __syncthreads();
    }
    float* Cz = C + (size_t)blockIdx.z * M * N;
    #pragma unroll
    for (int i = 0; i < TM; i++) {
        int m = m0 + ty*TM + i;
        #pragma unroll
        for (int j = 0; j < TN; j++)
            Cz[(size_t)m*N + n0 + tx*TN + j] = acc[i][j];
    }
}

// ---------------- small kernels ----------------
__device__ __forceinline__ float sigm(float x) { return 1.f/(1.f+expf(-x)); }

// split points: first t where s[n,t+1,:] all zero (argmax semantics: 0 if none)
__global__ void k_prep(const float* __restrict__ s)
{
    int n = threadIdx.x;
    if (n >= NB) return;
    int end = 0;
    for (int t = 1; t < TT; t++) {
        const float* p = s + ((size_t)n*TT + t)*SS;
        bool allz = true;
        for (int k = 0; k < SS; k++) { if (p[k] != 0.f) { allz = false; break; } }
        if (allz) { end = t - 1; break; }
    }
    g_end[n] = end;
    g_start[n] = end + 2;
}

__global__ void k_init_h()
{
    int idx = blockIdx.x*blockDim.x + threadIdx.x;
    if (idx < NB*LL) g_h[idx] = 1.0f;
}

// gather [t,n,k] encoder input: concat(s, a)
__global__ void k_gather_enc(const float* __restrict__ s, const float* __restrict__ a)
{
    int idx = blockIdx.x*blockDim.x + threadIdx.x;
    if (idx >= TENC*NB*160) return;
    int k = idx % 160;
    int n = (idx/160) % NB;
    int t = idx / (160*NB);
    g_xbuf[idx] = (k < SS) ? s[((size_t)n*TT+t)*SS + k]
                           : a[((size_t)n*TT+t)*AAd + (k-SS)];
}

// gather rolled decoder input a[n, (t+start)%T]
__global__ void k_gather_dec(const float* __restrict__ a)
{
    int idx = blockIdx.x*blockDim.x + threadIdx.x;
    if (idx >= TDEC*NB*AAd) return;
    int k = idx % AAd;
    int n = (idx/AAd) % NB;
    int t = idx / (AAd*NB);
    int src = (t + g_start[n]) % TT;
    g_abuf[idx] = a[((size_t)n*TT+src)*AAd + k];
}

// GRU pointwise: gates = xg + bih + (sum_ks gparts) + bhh; update h.
// enc mode snapshots hf at t==end[n]; dec mode stores h into outbuf.
__global__ void k_gru_point(const float* __restrict__ xg,
                            const float* __restrict__ bih,
                            const float* __restrict__ bhh,
                            float* __restrict__ h,
                            int t, int is_enc,
                            float* __restrict__ outbuf)
{
    int idx = blockIdx.x*blockDim.x + threadIdx.x;
    if (idx >= NB*LL) return;
    int n = idx >> 10, j = idx & 1023;
    float hr = 0.f, hz = 0.f, hn = 0.f;
    #pragma unroll
    for (int ks = 0; ks < KSPL; ks++) {
        const float* gp = g_gparts + (size_t)ks*NB*GG + (size_t)n*GG;
        hr += gp[j]; hz += gp[LL+j]; hn += gp[2*LL+j];
    }
    const float* xgn = xg + (size_t)n*GG;
    float r  = sigm(xgn[j]        + bih[j]        + hr + bhh[j]);
    float z  = sigm(xgn[LL+j]     + bih[LL+j]     + hz + bhh[LL+j]);
    float nn = tanhf(xgn[2*LL+j]  + bih[2*LL+j]   + r*(hn + bhh[2*LL+j]));
    float hp = h[idx];
    float hnew = (1.f - z)*nn + z*hp;
    h[idx] = hnew;
    if (is_enc) {
        if (t == g_end[n]) g_hf[idx] = hnew;
    } else {
        outbuf[idx] = hnew;
    }
}

// emb = mu + exp(lv/2)*eps, summing k-split GEMM partials + bias
__global__ void k_emb(const float* __restrict__ mu_b, const float* __restrict__ lv_b,
                      const float* __restrict__ eps)
{
    int idx = blockIdx.x*blockDim.x + threadIdx.x;
    if (idx >= NB*ZZ) return;
    int z = idx & 1023;
    float mu = mu_b[z], lv = lv_b[z];
    #pragma unroll
    for (int ks = 0; ks < 4; ks++) {
        mu += g_muparts[(size_t)ks*NB*ZZ + idx];
        lv += g_lvparts[(size_t)ks*NB*ZZ + idx];
    }
    g_emb[idx] = mu + expf(0.5f*lv)*eps[idx];
}

__global__ void k_relu_bias(float* __restrict__ y, const float* __restrict__ b,
                            int ncol, int total)
{
    int idx = blockIdx.x*blockDim.x + threadIdx.x;
    if (idx < total) y[idx] = fmaxf(y[idx] + b[idx % ncol], 0.f);
}

// masked L1 per (t,n) block -> deterministic partials
__global__ void k_loss(const float* __restrict__ d3b, const float* __restrict__ s_next)
{
    int bid = blockIdx.x;            // t*128 + n
    int t = bid >> 7, n = bid & 127;
    int st = g_start[n];
    int j = threadIdx.x;             // 128
    float v = 0.f;
    if (t < TT - st) {
        float pred = g_shat[(size_t)bid*SS + j] + d3b[j];
        int src = (t + st) % TT;
        v = fabsf(s_next[((size_t)n*TT+src)*SS + j] - pred);
    }
    __shared__ float sm[128];
    sm[j] = v; __syncthreads();
    for (int s2 = 64; s2 > 0; s2 >>= 1) {
        if (j < s2) sm[j] += sm[j+s2];
        __syncthreads();
    }
    if (j == 0) g_part[bid] = sm[0];
}

__global__ void k_reduce(float* __restrict__ out)
{
    __shared__ float sm[256];
    float acc = 0.f;
    for (int i = threadIdx.x; i < MDEC; i += 256) acc += g_part[i];
    sm[threadIdx.x] = acc; __syncthreads();
    for (int s2 = 128; s2 > 0; s2 >>= 1) {
        if (threadIdx.x < s2) sm[threadIdx.x] += sm[threadIdx.x+s2];
        __syncthreads();
    }
    if (threadIdx.x == 0) out[0] = sm[0];
}

// ---------------- host orchestration ----------------
extern "C" void kernel_launch(void* const* d_in, const int* in_sizes, int n_in,
                              void* d_out, int out_size)
{
    const float* s       = (const float*)d_in[0];
    const float* a       = (const float*)d_in[1];
    const float* s_next  = (const float*)d_in[3];
    const float* eps     = (const float*)d_in[4];
    const float* enc_Wih = (const float*)d_in[5];
    const float* enc_Whh = (const float*)d_in[6];
    const float* enc_bih = (const float*)d_in[7];
    const float* enc_bhh = (const float*)d_in[8];
    const float* mu_W    = (const float*)d_in[9];
    const float* mu_b    = (const float*)d_in[10];
    const float* lv_W    = (const float*)d_in[11];
    const float* lv_b    = (const float*)d_in[12];
    // d_in[13..18] = st* head: dead code in reference (unused)
    const float* dec_Wih = (const float*)d_in[19];
    const float* dec_Whh = (const float*)d_in[20];
    const float* dec_bih = (const float*)d_in[21];
    const float* dec_bhh = (const float*)d_in[22];
    const float* d1_W    = (const float*)d_in[23];
    const float* d1_b    = (const float*)d_in[24];
    const float* d2_W    = (const float*)d_in[25];
    const float* d2_b    = (const float*)d_in[26];
    const float* d3_W    = (const float*)d_in[27];
    const float* d3_b    = (const float*)d_in[28];

    float *xbuf, *xg_enc, *abuf, *xg_dec, *h, *hf, *gparts;
    float *muparts, *lvparts, *emb, *decout, *y1, *y2, *shat;
    cudaGetSymbolAddress((void**)&xbuf,    g_xbuf);
    cudaGetSymbolAddress((void**)&xg_enc,  g_xg_enc);
    cudaGetSymbolAddress((void**)&abuf,    g_abuf);
    cudaGetSymbolAddress((void**)&xg_dec,  g_xg_dec);
    cudaGetSymbolAddress((void**)&h,       g_h);
    cudaGetSymbolAddress((void**)&hf,      g_hf);
    cudaGetSymbolAddress((void**)&gparts,  g_gparts);
    cudaGetSymbolAddress((void**)&muparts, g_muparts);
    cudaGetSymbolAddress((void**)&lvparts, g_lvparts);
    cudaGetSymbolAddress((void**)&emb,     g_emb);
    cudaGetSymbolAddress((void**)&decout,  g_decout);
    cudaGetSymbolAddress((void**)&y1,      g_y1);
    cudaGetSymbolAddress((void**)&y2,      g_y2);
    cudaGetSymbolAddress((void**)&shat,    g_shat);

    // split points + encoder init
    k_prep<<<1, 128>>>(s);
    k_init_h<<<(NB*LL + 255)/256, 256>>>();

    // encoder input projection for all timesteps (parallel)
    k_gather_enc<<<(TENC*NB*160 + 255)/256, 256>>>(s, a);
    gemm_tn<<<dim3(GG/BN, TENC, 1), 256>>>(xbuf, enc_Wih, xg_enc,
                                           TENC*NB, GG, 160, 160, 160, 160);

    // encoder recurrence: 98 steps
    for (int t = 0; t < TENC; t++) {
        gemm_tn<<<dim3(GG/BN, 1, KSPL), 256>>>(h, enc_Whh, gparts,
                                               NB, GG, LL, LL, LL, LL/KSPL);
        k_gru_point<<<(NB*LL + 255)/256, 256>>>(xg_enc + (size_t)t*NB*GG,
                                                enc_bih, enc_bhh, h, t, 1, nullptr);
    }

    // reparametrize
    gemm_tn<<<dim3(ZZ/BN, 1, 4), 256>>>(hf, mu_W, muparts, NB, ZZ, LL, LL, LL, LL/4);
    gemm_tn<<<dim3(ZZ/BN, 1, 4), 256>>>(hf, lv_W, lvparts, NB, ZZ, LL, LL, LL, LL/4);
    k_emb<<<(NB*ZZ + 255)/256, 256>>>(mu_b, lv_b, eps);

    // decoder input projection (rolled actions), only 49 needed steps
    k_gather_dec<<<(TDEC*NB*AAd + 255)/256, 256>>>(a);
    gemm_tn<<<dim3(GG/BN, TDEC, 1), 256>>>(abuf, dec_Wih, xg_dec,
                                           MDEC, GG, AAd, AAd, AAd, AAd);

    // decoder recurrence: 49 steps, h0 = emb
    for (int t = 0; t < TDEC; t++) {
        gemm_tn<<<dim3(GG/BN, 1, KSPL), 256>>>(emb, dec_Whh, gparts,
                                               NB, GG, ZZ, ZZ, ZZ, ZZ/KSPL);
        k_gru_point<<<(NB*LL + 255)/256, 256>>>(xg_dec + (size_t)t*NB*GG,
                                                dec_bih, dec_bhh, emb, t, 0,
                                                decout + (size_t)t*NB*ZZ);
    }

    // decoder MLP head as batched GEMMs over all (t,n)
    gemm_tn<<<dim3(128/BN, MDEC/BM, 1), 256>>>(decout, d1_W, y1,
                                               MDEC, 128, ZZ, ZZ, ZZ, ZZ);
    k_relu_bias<<<(MDEC*128 + 255)/256, 256>>>(y1, d1_b, 128, MDEC*128);
    gemm_tn<<<dim3(64/BN, MDEC/BM, 1), 256>>>(y1, d2_W, y2,
                                              MDEC, 64, 128, 128, 128, 128);
    k_relu_bias<<<(MDEC*64 + 255)/256, 256>>>(y2, d2_b, 64, MDEC*64);
    gemm_tn<<<dim3(128/BN, MDEC/BM, 1), 256>>>(y2, d3_W, shat,
                                               MDEC, 128, 64, 64, 64, 64);

    // masked L1 loss, deterministic two-stage reduction
    k_loss<<<MDEC, 128>>>(d3_b, s_next);
    k_reduce<<<1, 256>>>((float*)d_out);
}

// round 4
// speedup vs baseline: 1.4329x; 1.4329x over previous
#include <cuda_runtime.h>
#include <math.h>
#include <stdint.h>

// ---------------- problem constants ----------------
#define NB   128
#define TT   100
#define SS   128
#define AAd  32
#define LL   1024
#define GG   3072
#define TENC 98
#define TDEC 49
#define MDEC (TDEC*NB)

// recurrence kernel geometry
#define RCTAS 128          // persistent CTAs (<=148 -> all co-resident)
#define HPC   8            // hidden cols per CTA
#define NT    3            // n-tiles (24 gate cols: r|z|n x 8)
#define KS    64           // k-steps of 16 (K=1024)
#define SMEMB (KS*NT*32*4*4 + 64*4)   // weight frags (96KB) + biases

// ---------------- device scratch ----------------
__device__ float    g_xbuf  [TENC*NB*160];
__device__ float    g_xg_enc[TENC*(size_t)NB*GG];
__device__ float    g_abuf  [TDEC*NB*AAd];
__device__ float    g_xg_dec[TDEC*(size_t)NB*GG];
__device__ unsigned g_hhi   [2][NB*512];   // h hi-plane: bf16x2 pairs, ping-pong
__device__ unsigned g_hlo   [2][NB*512];   // h lo-plane (residual)
__device__ float    g_hf    [NB*LL];
__device__ float    g_muparts[4*NB*LL];
__device__ float    g_lvparts[4*NB*LL];
__device__ float    g_emb   [NB*LL];
__device__ float    g_decout[TDEC*(size_t)NB*LL];
__device__ float    g_y1    [MDEC*128];
__device__ float    g_y2    [MDEC*64];
__device__ float    g_shat  [MDEC*128];
__device__ float    g_part  [MDEC];
__device__ int      g_end   [NB];
__device__ int      g_start [NB];
__device__ unsigned g_barrier;

// ---------------- bf16 bit helpers ----------------
__device__ __forceinline__ unsigned f2bf(float x) {            // RNE to bf16 bits
    unsigned u = __float_as_uint(x);
    return (u + 0x7FFFu + ((u >> 16) & 1u)) >> 16;
}
__device__ __forceinline__ unsigned packbf(float x, float y) { // low=x, high=y
    return f2bf(x) | (f2bf(y) << 16);
}
__device__ __forceinline__ float bflo(unsigned p) { return __uint_as_float(p << 16); }
__device__ __forceinline__ float bfhi(unsigned p) { return __uint_as_float(p & 0xFFFF0000u); }

__device__ __forceinline__ void mma16816(float* c, const unsigned* a,
                                         unsigned b0, unsigned b1) {
    asm volatile(
        "mma.sync.aligned.m16n8k16.row.col.f32.bf16.bf16.f32 "
        "{%0,%1,%2,%3}, {%4,%5,%6,%7}, {%8,%9}, {%0,%1,%2,%3};"
        : "+f"(c[0]), "+f"(c[1]), "+f"(c[2]), "+f"(c[3])
        : "r"(a[0]), "r"(a[1]), "r"(a[2]), "r"(a[3]), "r"(b0), "r"(b1));
}

__device__ __forceinline__ float sigmf_(float x) { return 1.f / (1.f + __expf(-x)); }
__device__ __forceinline__ float tanhf_(float x) {
    float e = __expf(2.f * fabsf(x));
    return copysignf(1.f - 2.f / (e + 1.f), x);
}

// ============ persistent GRU recurrence ============
// 128 CTAs x 256 thr. CTA b owns hidden cols [8b,8b+8) -> gate cols {g*1024+8b..}.
// Per step: gates[128,24] = h[128,1024] @ Wslice^T via bf16x3 mma.sync,
// fused GRU pointwise, global grid barrier, ping-pong h planes.
__global__ __launch_bounds__(256, 1)
void gru_persist(const float* __restrict__ Whh,
                 const float* __restrict__ xg_all,
                 const float* __restrict__ bih,
                 const float* __restrict__ bhh,
                 int T, int mode, float* __restrict__ decout)
{
    extern __shared__ unsigned dyn[];
    unsigned* sW = dyn;                         // KS*NT*32*4 u32
    float* sb = (float*)(dyn + KS*NT*32*4);     // 48 floats: bih r|z|n, bhh r|z|n

    int tid = threadIdx.x;
    int hc0 = blockIdx.x * HPC;

    // ---- one-time: pack weight slice into mma-ready bf16 hi/lo fragments ----
    for (int idx = tid; idx < KS*NT*32; idx += 256) {
        int lane = idx & 31;
        int nt   = (idx >> 5) % NT;
        int ks   = idx / (NT*32);
        int t4   = lane & 3;
        int grow = nt*1024 + hc0 + (lane >> 2);          // gate row in Whh
        const float* wr = Whh + (size_t)grow*LL + ks*16 + 2*t4;
        float w0 = wr[0], w1 = wr[1], w2 = wr[8], w3 = wr[9];
        unsigned bh0 = packbf(w0, w1), bh1 = packbf(w2, w3);
        float l0 = w0 - bflo(bh0), l1 = w1 - bfhi(bh0);
        float l2 = w2 - bflo(bh1), l3 = w3 - bfhi(bh1);
        unsigned* d = sW + (size_t)idx*4;
        d[0] = bh0; d[1] = bh1;
        d[2] = packbf(l0, l1); d[3] = packbf(l2, l3);
    }
    if (tid < 6*HPC) {
        int gate = tid / HPC, j = tid % HPC;
        const float* src = (gate < 3) ? bih : bhh;
        sb[tid] = src[(gate % 3)*1024 + hc0 + j];
    }
    __syncthreads();

    int w = tid >> 5, lane = tid & 31;
    int g = lane >> 2, t4 = lane & 3;
    int r0 = w*16 + g, r1 = r0 + 8;
    int e0 = -1, e1 = -1;
    if (mode == 0) { e0 = g_end[r0]; e1 = g_end[r1]; }

    int jb = 2*t4;               // col pair within CTA's 8
    int colg = hc0 + jb;
    int pidx = colg >> 1;        // u32 pair index within a row (512 per row)

    for (int t = 0; t < T; t++) {
        int rb = t & 1;
        const unsigned* hiP = g_hhi[rb];
        const unsigned* loP = g_hlo[rb];
        unsigned* whiP = g_hhi[rb ^ 1];
        unsigned* wloP = g_hlo[rb ^ 1];

        float acc[NT][4];
        #pragma unroll
        for (int n = 0; n < NT; n++)
            #pragma unroll
            for (int c = 0; c < 4; c++) acc[n][c] = 0.f;

        int ao0 = r0*512 + t4, ao1 = r1*512 + t4;
        #pragma unroll 2
        for (int ks = 0; ks < KS; ks++) {
            unsigned ahi[4], alo[4];
            int o0 = ao0 + ks*8, o1 = ao1 + ks*8;
            ahi[0] = __ldcg(hiP + o0);     ahi[1] = __ldcg(hiP + o1);
            ahi[2] = __ldcg(hiP + o0 + 4); ahi[3] = __ldcg(hiP + o1 + 4);
            alo[0] = __ldcg(loP + o0);     alo[1] = __ldcg(loP + o1);
            alo[2] = __ldcg(loP + o0 + 4); alo[3] = __ldcg(loP + o1 + 4);
            #pragma unroll
            for (int nt = 0; nt < NT; nt++) {
                uint4 b = *(const uint4*)(sW + (size_t)((ks*NT + nt)*32 + lane)*4);
                mma16816(acc[nt], ahi, b.x, b.y);   // hi*hi
                mma16816(acc[nt], alo, b.x, b.y);   // lo_A*hi_B
                mma16816(acc[nt], ahi, b.z, b.w);   // hi_A*lo_B
            }
        }

        // ---- fused GRU pointwise ----
        const float* xg = xg_all + (size_t)t*NB*GG;
        #pragma unroll
        for (int p = 0; p < 2; p++) {
            int row = p ? r1 : r0;
            int c = 2*p;
            float2 xr = *(const float2*)(xg + (size_t)row*GG + colg);
            float2 xz = *(const float2*)(xg + (size_t)row*GG + 1024 + colg);
            float2 xn = *(const float2*)(xg + (size_t)row*GG + 2048 + colg);
            unsigned ph = __ldcg(hiP + row*512 + pidx);
            unsigned pl = __ldcg(loP + row*512 + pidx);
            float hp0 = bflo(ph) + bflo(pl);
            float hp1 = bfhi(ph) + bfhi(pl);

            float rr0 = sigmf_(xr.x + sb[jb]      + acc[0][c]   + sb[24+jb]);
            float rr1 = sigmf_(xr.y + sb[jb+1]    + acc[0][c+1] + sb[24+jb+1]);
            float zz0 = sigmf_(xz.x + sb[8+jb]    + acc[1][c]   + sb[32+jb]);
            float zz1 = sigmf_(xz.y + sb[8+jb+1]  + acc[1][c+1] + sb[32+jb+1]);
            float nn0 = tanhf_(xn.x + sb[16+jb]   + rr0*(acc[2][c]   + sb[40+jb]));
            float nn1 = tanhf_(xn.y + sb[16+jb+1] + rr1*(acc[2][c+1] + sb[40+jb+1]));
            float h0 = (1.f - zz0)*nn0 + zz0*hp0;
            float h1 = (1.f - zz1)*nn1 + zz1*hp1;

            unsigned hiw = packbf(h0, h1);
            float l0 = h0 - bflo(hiw), l1 = h1 - bfhi(hiw);
            whiP[row*512 + pidx] = hiw;
            wloP[row*512 + pidx] = packbf(l0, l1);

            if (mode == 0) {
                if (t == (p ? e1 : e0)) {
                    float2 v; v.x = h0; v.y = h1;
                    *(float2*)(g_hf + (size_t)row*LL + colg) = v;
                }
            } else {
                float2 v; v.x = h0; v.y = h1;
                *(float2*)(decout + ((size_t)t*NB + row)*LL + colg) = v;
            }
        }

        // ---- grid barrier (skip after last step) ----
        if (t + 1 < T) {
            __threadfence();
            __syncthreads();
            if (tid == 0) {
                atomicAdd(&g_barrier, 1u);
                unsigned target = (unsigned)(RCTAS*(t + 1));
                unsigned v;
                do {
                    asm volatile("ld.global.cg.u32 %0, [%1];" : "=r"(v) : "l"(&g_barrier));
                } while (v < target);
                __threadfence();
            }
            __syncthreads();
        }
    }
}

__global__ void k_zero_barrier() { if (threadIdx.x == 0) g_barrier = 0u; }

// ---------------- fp32 TN GEMM (projection / heads) ----------------
#define BM 128
#define BN 64
#define BK 16
#define TM 8
#define TN 4

__global__ __launch_bounds__(256)
void gemm_tn(const float* __restrict__ A, const float* __restrict__ B,
             float* __restrict__ C, int M, int N, int K,
             int lda, int ldb, int klen)
{
    __shared__ float As[BK][BM+1];
    __shared__ float Bs[BK][BN+1];
    int tid = threadIdx.x;
    int m0 = blockIdx.y * BM;
    int n0 = blockIdx.x * BN;
    int k0 = blockIdx.z * klen;
    int kend = k0 + klen; if (kend > K) kend = K;
    int tx = tid & 15, ty = tid >> 4;

    float acc[TM][TN];
    #pragma unroll
    for (int i = 0; i < TM; i++)
        #pragma unroll
        for (int j = 0; j < TN; j++) acc[i][j] = 0.f;

    for (int kb = k0; kb < kend; kb += BK) {
        #pragma unroll
        for (int r = 0; r < (BK*BM)/256; r++) {
            int e = r*256 + tid;
            int kk = e & (BK-1);
            int mm = e >> 4;
            As[kk][mm] = A[(size_t)(m0+mm)*lda + kb + kk];
        }
        #pragma unroll
        for (int r = 0; r < (BK*BN)/256; r++) {
            int e = r*256 + tid;
            int kk = e & (BK-1);
            int nn = e >> 4;
            Bs[kk][nn] = B[(size_t)(n0+nn)*ldb + kb + kk];
        }
        __syncthreads();
        #pragma unroll
        for (int kk = 0; kk < BK; kk++) {
            float ra[TM], rb[TN];
            #pragma unroll
            for (int i = 0; i < TM; i++) ra[i] = As[kk][ty*TM+i];
            #pragma unroll
            for (int j = 0; j < TN; j++) rb[j] = Bs[kk][tx*TN+j];
            #pragma unroll
            for (int i = 0; i < TM; i++)
                #pragma unroll
                for (int j = 0; j < TN; j++)
                    acc[i][j] = fmaf(ra[i], rb[j], acc[i][j]);
        }
        __syncthreads();
    }
    float* Cz = C + (size_t)blockIdx.z * M * N;
    #pragma unroll
    for (int i = 0; i < TM; i++) {
        int m = m0 + ty*TM + i;
        #pragma unroll
        for (int j = 0; j < TN; j++)
            Cz[(size_t)m*N + n0 + tx*TN + j] = acc[i][j];
    }
}

// ---------------- small kernels ----------------
__global__ void k_prep(const float* __restrict__ s)
{
    int n = threadIdx.x;
    if (n >= NB) return;
    int end = 0;
    for (int t = 1; t < TT; t++) {
        const float* p = s + ((size_t)n*TT + t)*SS;
        bool allz = true;
        for (int k = 0; k < SS; k++) { if (p[k] != 0.f) { allz = false; break; } }
        if (allz) { end = t - 1; break; }
    }
    g_end[n] = end;
    g_start[n] = end + 2;
}

__global__ void k_seed_ones()
{
    int idx = blockIdx.x*blockDim.x + threadIdx.x;
    if (idx < NB*512) { g_hhi[0][idx] = 0x3F803F80u; g_hlo[0][idx] = 0u; }
}

__global__ void k_seed_emb()
{
    int idx = blockIdx.x*blockDim.x + threadIdx.x;
    if (idx >= NB*512) return;
    float2 e = ((const float2*)g_emb)[idx];
    unsigned hi = packbf(e.x, e.y);
    float l0 = e.x - bflo(hi), l1 = e.y - bfhi(hi);
    g_hhi[0][idx] = hi;
    g_hlo[0][idx] = packbf(l0, l1);
}

__global__ void k_gather_enc(const float* __restrict__ s, const float* __restrict__ a)
{
    int idx = blockIdx.x*blockDim.x + threadIdx.x;
    if (idx >= TENC*NB*160) return;
    int k = idx % 160;
    int n = (idx/160) % NB;
    int t = idx / (160*NB);
    g_xbuf[idx] = (k < SS) ? s[((size_t)n*TT+t)*SS + k]
                           : a[((size_t)n*TT+t)*AAd + (k-SS)];
}

__global__ void k_gather_dec(const float* __restrict__ a)
{
    int idx = blockIdx.x*blockDim.x + threadIdx.x;
    if (idx >= TDEC*NB*AAd) return;
    int k = idx % AAd;
    int n = (idx/AAd) % NB;
    int t = idx / (AAd*NB);
    int src = (t + g_start[n]) % TT;
    g_abuf[idx] = a[((size_t)n*TT+src)*AAd + k];
}

__global__ void k_emb(const float* __restrict__ mu_b, const float* __restrict__ lv_b,
                      const float* __restrict__ eps)
{
    int idx = blockIdx.x*blockDim.x + threadIdx.x;
    if (idx >= NB*LL) return;
    int z = idx & 1023;
    float mu = mu_b[z], lv = lv_b[z];
    #pragma unroll
    for (int ks = 0; ks < 4; ks++) {
        mu += g_muparts[(size_t)ks*NB*LL + idx];
        lv += g_lvparts[(size_t)ks*NB*LL + idx];
    }
    g_emb[idx] = mu + expf(0.5f*lv)*eps[idx];
}

__global__ void k_relu_bias(float* __restrict__ y, const float* __restrict__ b,
                            int ncol, int total)
{
    int idx = blockIdx.x*blockDim.x + threadIdx.x;
    if (idx < total) y[idx] = fmaxf(y[idx] + b[idx % ncol], 0.f);
}

__global__ void k_loss(const float* __restrict__ d3b, const float* __restrict__ s_next)
{
    int bid = blockIdx.x;            // t*128 + n
    int t = bid >> 7, n = bid & 127;
    int st = g_start[n];
    int j = threadIdx.x;
    float v = 0.f;
    if (t < TT - st) {
        float pred = g_shat[(size_t)bid*SS + j] + d3b[j];
        int src = (t + st) % TT;
        v = fabsf(s_next[((size_t)n*TT+src)*SS + j] - pred);
    }
    __shared__ float sm[128];
    sm[j] = v; __syncthreads();
    for (int s2 = 64; s2 > 0; s2 >>= 1) {
        if (j < s2) sm[j] += sm[j+s2];
        __syncthreads();
    }
    if (j == 0) g_part[bid] = sm[0];
}

__global__ void k_reduce(float* __restrict__ out)
{
    __shared__ float sm[256];
    float acc = 0.f;
    for (int i = threadIdx.x; i < MDEC; i += 256) acc += g_part[i];
    sm[threadIdx.x] = acc; __syncthreads();
    for (int s2 = 128; s2 > 0; s2 >>= 1) {
        if (threadIdx.x < s2) sm[threadIdx.x] += sm[threadIdx.x+s2];
        __syncthreads();
    }
    if (threadIdx.x == 0) out[0] = sm[0];
}

// ---------------- host orchestration ----------------
extern "C" void kernel_launch(void* const* d_in, const int* in_sizes, int n_in,
                              void* d_out, int out_size)
{
    const float* s       = (const float*)d_in[0];
    const float* a       = (const float*)d_in[1];
    const float* s_next  = (const float*)d_in[3];
    const float* eps     = (const float*)d_in[4];
    const float* enc_Wih = (const float*)d_in[5];
    const float* enc_Whh = (const float*)d_in[6];
    const float* enc_bih = (const float*)d_in[7];
    const float* enc_bhh = (const float*)d_in[8];
    const float* mu_W    = (const float*)d_in[9];
    const float* mu_b    = (const float*)d_in[10];
    const float* lv_W    = (const float*)d_in[11];
    const float* lv_b    = (const float*)d_in[12];
    const float* dec_Wih = (const float*)d_in[19];
    const float* dec_Whh = (const float*)d_in[20];
    const float* dec_bih = (const float*)d_in[21];
    const float* dec_bhh = (const float*)d_in[22];
    const float* d1_W    = (const float*)d_in[23];
    const float* d1_b    = (const float*)d_in[24];
    const float* d2_W    = (const float*)d_in[25];
    const float* d2_b    = (const float*)d_in[26];
    const float* d3_W    = (const float*)d_in[27];
    const float* d3_b    = (const float*)d_in[28];

    float *xbuf, *xg_enc, *abuf, *xg_dec, *hf;
    float *muparts, *lvparts, *emb, *decout, *y1, *y2, *shat;
    cudaGetSymbolAddress((void**)&xbuf,    g_xbuf);
    cudaGetSymbolAddress((void**)&xg_enc,  g_xg_enc);
    cudaGetSymbolAddress((void**)&abuf,    g_abuf);
    cudaGetSymbolAddress((void**)&xg_dec,  g_xg_dec);
    cudaGetSymbolAddress((void**)&hf,      g_hf);
    cudaGetSymbolAddress((void**)&muparts, g_muparts);
    cudaGetSymbolAddress((void**)&lvparts, g_lvparts);
    cudaGetSymbolAddress((void**)&emb,     g_emb);
    cudaGetSymbolAddress((void**)&decout,  g_decout);
    cudaGetSymbolAddress((void**)&y1,      g_y1);
    cudaGetSymbolAddress((void**)&y2,      g_y2);
    cudaGetSymbolAddress((void**)&shat,    g_shat);

    cudaFuncSetAttribute(gru_persist, cudaFuncAttributeMaxDynamicSharedMemorySize,
                         SMEMB);

    // split points + encoder init
    k_prep<<<1, 128>>>(s);
    k_seed_ones<<<(NB*512 + 255)/256, 256>>>();

    // encoder input projection for all timesteps (parallel)
    k_gather_enc<<<(TENC*NB*160 + 255)/256, 256>>>(s, a);
    gemm_tn<<<dim3(GG/BN, TENC, 1), 256>>>(xbuf, enc_Wih, xg_enc,
                                           TENC*NB, GG, 160, 160, 160, 160);

    // encoder recurrence: ONE persistent launch, 98 steps
    k_zero_barrier<<<1, 32>>>();
    gru_persist<<<RCTAS, 256, SMEMB>>>(enc_Whh, xg_enc, enc_bih, enc_bhh,
                                       TENC, 0, nullptr);

    // reparametrize
    gemm_tn<<<dim3(LL/BN, 1, 4), 256>>>(hf, mu_W, muparts, NB, LL, LL, LL, LL, LL/4);
    gemm_tn<<<dim3(LL/BN, 1, 4), 256>>>(hf, lv_W, lvparts, NB, LL, LL, LL, LL, LL/4);
    k_emb<<<(NB*LL + 255)/256, 256>>>(mu_b, lv_b, eps);
    k_seed_emb<<<(NB*512 + 255)/256, 256>>>();

    // decoder input projection (rolled actions)
    k_gather_dec<<<(TDEC*NB*AAd + 255)/256, 256>>>(a);
    gemm_tn<<<dim3(GG/BN, TDEC, 1), 256>>>(abuf, dec_Wih, xg_dec,
                                           MDEC, GG, AAd, AAd, AAd, AAd);

    // decoder recurrence: ONE persistent launch, 49 steps
    k_zero_barrier<<<1, 32>>>();
    gru_persist<<<RCTAS, 256, SMEMB>>>(dec_Whh, xg_dec, dec_bih, dec_bhh,
                                       TDEC, 1, decout);

    // decoder MLP head
    gemm_tn<<<dim3(128/BN, MDEC/BM, 1), 256>>>(decout, d1_W, y1,
                                               MDEC, 128, LL, LL, LL, LL);
    k_relu_bias<<<(MDEC*128 + 255)/256, 256>>>(y1, d1_b, 128, MDEC*128);
    gemm_tn<<<dim3(64/BN, MDEC/BM, 1), 256>>>(y1, d2_W, y2,
                                              MDEC, 64, 128, 128, 128, 128);
    k_relu_bias<<<(MDEC*64 + 255)/256, 256>>>(y2, d2_b, 64, MDEC*64);
    gemm_tn<<<dim3(128/BN, MDEC/BM, 1), 256>>>(y2, d3_W, shat,
                                               MDEC, 128, 64, 64, 64, 64);

    // masked L1 loss, deterministic two-stage reduction
    k_loss<<<MDEC, 128>>>(d3_b, s_next);
    k_reduce<<<1, 256>>>((float*)d_out);
}

// round 5
// speedup vs baseline: 1.9436x; 1.3565x over previous
#include <cuda_runtime.h>
#include <math.h>
#include <stdint.h>

// ---------------- problem constants ----------------
#define NB   128
#define TT   100
#define SS   128
#define AAd  32
#define LL   1024
#define GG   3072
#define TENC 98
#define TDEC 49
#define MDEC (TDEC*NB)

// recurrence kernel geometry
#define RCTAS  128         // persistent CTAs
#define HPC    8           // hidden cols per CTA
#define NT     3           // n-tiles (r|z|n gates x 8 cols)
#define KS     64          // k-steps of 16 (K=1024)
#define CHUNKS 16          // k-chunks of 64 per step
#define APITCH 36          // u32 per staged row (144B, conflict-free ldmatrix)
#define APLANE (128*APITCH)      // u32 per plane  = 4608
#define ABUF   (2*APLANE)        // u32 per buffer = 9216 (hi+lo)
#define SW_U32 (KS*NT*32*4)      // 24576 u32 weight frags
#define SA_OFF (SW_U32 + 64)     // u32 offset of A staging (16B aligned)
#define SMEM2  ((SA_OFF + 3*ABUF)*4)   // 209152 bytes

// ---------------- device scratch ----------------
__device__ float    g_xbuf  [TENC*NB*160];
__device__ float    g_xg_enc[TENC*(size_t)NB*GG];
__device__ float    g_abuf  [TDEC*NB*AAd];
__device__ float    g_xg_dec[TDEC*(size_t)NB*GG];
__device__ unsigned g_hhi   [2][NB*512];   // h hi-plane: bf16x2, ping-pong
__device__ unsigned g_hlo   [2][NB*512];   // h lo-plane (residual)
__device__ float    g_hf    [NB*LL];
__device__ float    g_muparts[4*NB*LL];
__device__ float    g_lvparts[4*NB*LL];
__device__ float    g_emb   [NB*LL];
__device__ float    g_decout[TDEC*(size_t)NB*LL];
__device__ float    g_y1    [MDEC*128];
__device__ float    g_y2    [MDEC*64];
__device__ float    g_shat  [MDEC*128];
__device__ float    g_part  [MDEC];
__device__ int      g_end   [NB];
__device__ int      g_start [NB];
__device__ unsigned g_barrier;

// ---------------- bf16 bit helpers ----------------
__device__ __forceinline__ unsigned f2bf(float x) {            // RNE to bf16 bits
    unsigned u = __float_as_uint(x);
    return (u + 0x7FFFu + ((u >> 16) & 1u)) >> 16;
}
__device__ __forceinline__ unsigned packbf(float x, float y) { // low=x, high=y
    return f2bf(x) | (f2bf(y) << 16);
}
__device__ __forceinline__ float bflo(unsigned p) { return __uint_as_float(p << 16); }
__device__ __forceinline__ float bfhi(unsigned p) { return __uint_as_float(p & 0xFFFF0000u); }

__device__ __forceinline__ void mma16816(float* c, const unsigned* a,
                                         unsigned b0, unsigned b1) {
    asm volatile(
        "mma.sync.aligned.m16n8k16.row.col.f32.bf16.bf16.f32 "
        "{%0,%1,%2,%3}, {%4,%5,%6,%7}, {%8,%9}, {%0,%1,%2,%3};"
        : "+f"(c[0]), "+f"(c[1]), "+f"(c[2]), "+f"(c[3])
        : "r"(a[0]), "r"(a[1]), "r"(a[2]), "r"(a[3]), "r"(b0), "r"(b1));
}
#define LDMX4(a, addr) asm volatile(                                        \
    "ldmatrix.sync.aligned.m8n8.x4.shared.b16 {%0,%1,%2,%3}, [%4];"         \
    : "=r"((a)[0]), "=r"((a)[1]), "=r"((a)[2]), "=r"((a)[3]) : "r"(addr))

__device__ __forceinline__ uint32_t smem_u32(const void* p) {
    uint32_t a;
    asm("{ .reg .u64 t; cvta.to.shared.u64 t, %1; cvt.u32.u64 %0, t; }"
        : "=r"(a) : "l"(p));
    return a;
}
__device__ __forceinline__ void cp16(uint32_t s, const void* g) {
    asm volatile("cp.async.cg.shared.global [%0], [%1], 16;" :: "r"(s), "l"(g));
}
__device__ __forceinline__ void cp_commit() { asm volatile("cp.async.commit_group;"); }
template<int N> __device__ __forceinline__ void cp_wait() {
    asm volatile("cp.async.wait_group %0;" :: "n"(N));
}

__device__ __forceinline__ float sigmf_(float x) { return 1.f / (1.f + __expf(-x)); }
__device__ __forceinline__ float tanhf_(float x) {
    float e = __expf(2.f * fabsf(x));
    return copysignf(1.f - 2.f / (e + 1.f), x);
}

// stage one 64-k-col chunk (both planes) into smem buffer via cp.async
__device__ __forceinline__ void stage_chunk(uint32_t sbuf, const unsigned* hiP,
                                            const unsigned* loP, int c, int tid)
{
    #pragma unroll
    for (int r = 0; r < 4; r++) {
        int j = tid + r*256;            // 0..1023
        int row = j >> 3, seg = j & 7;
        uint32_t so = sbuf + row*144 + seg*16;
        const char* gh = (const char*)hiP + row*2048 + c*128 + seg*16;
        const char* gl = (const char*)loP + row*2048 + c*128 + seg*16;
        cp16(so, gh);
        cp16(so + APLANE*4, gl);
    }
    cp_commit();
}

// ============ persistent GRU recurrence (v2: cp.async + ldmatrix) ============
__global__ __launch_bounds__(256, 1)
void gru_persist(const float* __restrict__ Whh,
                 const float* __restrict__ xg_all,
                 const float* __restrict__ bih,
                 const float* __restrict__ bhh,
                 int T, int mode, float* __restrict__ decout)
{
    extern __shared__ unsigned dyn[];
    unsigned* sW = dyn;                      // weight frags
    float* sb = (float*)(dyn + SW_U32);      // 48 biases
    uint32_t sA0 = smem_u32(dyn + SA_OFF);   // byte addr of A buffer 0

    int tid = threadIdx.x;
    int hc0 = blockIdx.x * HPC;

    // ---- one-time: pack weight slice into mma-ready bf16 hi/lo fragments ----
    for (int idx = tid; idx < KS*NT*32; idx += 256) {
        int lane = idx & 31;
        int nt   = (idx >> 5) % NT;
        int ks   = idx / (NT*32);
        int t4   = lane & 3;
        int grow = nt*1024 + hc0 + (lane >> 2);
        const float* wr = Whh + (size_t)grow*LL + ks*16 + 2*t4;
        float w0 = wr[0], w1 = wr[1], w2 = wr[8], w3 = wr[9];
        unsigned bh0 = packbf(w0, w1), bh1 = packbf(w2, w3);
        float l0 = w0 - bflo(bh0), l1 = w1 - bfhi(bh0);
        float l2 = w2 - bflo(bh1), l3 = w3 - bfhi(bh1);
        unsigned* d = sW + (size_t)idx*4;
        d[0] = bh0; d[1] = bh1;
        d[2] = packbf(l0, l1); d[3] = packbf(l2, l3);
    }
    if (tid < 6*HPC) {
        int gate = tid / HPC, j = tid % HPC;
        const float* src = (gate < 3) ? bih : bhh;
        sb[tid] = src[(gate % 3)*1024 + hc0 + j];
    }
    __syncthreads();

    int w = tid >> 5, lane = tid & 31;
    int g = lane >> 2, t4 = lane & 3;
    int r0 = w*16 + g, r1 = r0 + 8;
    int e0 = -1, e1 = -1;
    if (mode == 0) { e0 = g_end[r0]; e1 = g_end[r1]; }

    int jb = 2*t4;
    int colg = hc0 + jb;
    int pidx = colg >> 1;

    // ldmatrix per-lane address offset (canonical x4 pattern, 144B row pitch)
    int m2 = lane >> 3, r8 = lane & 7;
    uint32_t ldm_off = (uint32_t)((w*16 + ((m2 & 1) << 3) + r8)*144 + (m2 >> 1)*16);

    // register-carried h for this thread's 4 owned elements
    float hprev[4];
    {
        unsigned p0 = g_hhi[0][r0*512 + pidx], q0 = g_hlo[0][r0*512 + pidx];
        unsigned p1 = g_hhi[0][r1*512 + pidx], q1 = g_hlo[0][r1*512 + pidx];
        hprev[0] = bflo(p0) + bflo(q0); hprev[1] = bfhi(p0) + bfhi(q0);
        hprev[2] = bflo(p1) + bflo(q1); hprev[3] = bfhi(p1) + bfhi(q1);
    }

    #pragma unroll 1
    for (int t = 0; t < T; t++) {
        int rb = t & 1;
        const unsigned* hiP = g_hhi[rb];
        const unsigned* loP = g_hlo[rb];
        unsigned* whiP = g_hhi[rb ^ 1];
        unsigned* wloP = g_hlo[rb ^ 1];

        float acc[NT][4];
        #pragma unroll
        for (int n = 0; n < NT; n++)
            #pragma unroll
            for (int c = 0; c < 4; c++) acc[n][c] = 0.f;

        // prologue: stage chunks 0,1
        stage_chunk(sA0,              hiP, loP, 0, tid);
        stage_chunk(sA0 + ABUF*4,     hiP, loP, 1, tid);

        #pragma unroll 1
        for (int c = 0; c < CHUNKS; c++) {
            if (c + 1 < CHUNKS) { cp_wait<1>(); } else { cp_wait<0>(); }
            __syncthreads();                      // chunk c visible; c-1 consumers done
            if (c + 2 < CHUNKS)
                stage_chunk(sA0 + (uint32_t)((c + 2) % 3)*ABUF*4, hiP, loP, c + 2, tid);

            uint32_t hb = sA0 + (uint32_t)(c % 3)*ABUF*4 + ldm_off;
            #pragma unroll
            for (int ksl = 0; ksl < 4; ksl++) {
                uint32_t ahi[4], alo[4];
                uint32_t ad = hb + ksl*32;
                LDMX4(ahi, ad);
                LDMX4(alo, ad + APLANE*4);
                int ksg = c*4 + ksl;
                #pragma unroll
                for (int nt = 0; nt < NT; nt++) {
                    uint4 b = *(const uint4*)(sW + (size_t)((ksg*NT + nt)*32 + lane)*4);
                    mma16816(acc[nt], ahi, b.x, b.y);   // hi*hi
                    mma16816(acc[nt], alo, b.x, b.y);   // lo_A*hi_B
                    mma16816(acc[nt], ahi, b.z, b.w);   // hi_A*lo_B
                }
            }
        }

        // ---- fused GRU pointwise (h carried in registers) ----
        const float* xg = xg_all + (size_t)t*NB*GG;
        #pragma unroll
        for (int p = 0; p < 2; p++) {
            int row = p ? r1 : r0;
            int c = 2*p;
            float2 xr = *(const float2*)(xg + (size_t)row*GG + colg);
            float2 xz = *(const float2*)(xg + (size_t)row*GG + 1024 + colg);
            float2 xn = *(const float2*)(xg + (size_t)row*GG + 2048 + colg);

            float rr0 = sigmf_(xr.x + sb[jb]      + acc[0][c]   + sb[24+jb]);
            float rr1 = sigmf_(xr.y + sb[jb+1]    + acc[0][c+1] + sb[24+jb+1]);
            float zz0 = sigmf_(xz.x + sb[8+jb]    + acc[1][c]   + sb[32+jb]);
            float zz1 = sigmf_(xz.y + sb[8+jb+1]  + acc[1][c+1] + sb[32+jb+1]);
            float nn0 = tanhf_(xn.x + sb[16+jb]   + rr0*(acc[2][c]   + sb[40+jb]));
            float nn1 = tanhf_(xn.y + sb[16+jb+1] + rr1*(acc[2][c+1] + sb[40+jb+1]));
            float h0 = (1.f - zz0)*nn0 + zz0*hprev[c];
            float h1 = (1.f - zz1)*nn1 + zz1*hprev[c+1];
            hprev[c] = h0; hprev[c+1] = h1;

            unsigned hiw = packbf(h0, h1);
            whiP[row*512 + pidx] = hiw;
            wloP[row*512 + pidx] = packbf(h0 - bflo(hiw), h1 - bfhi(hiw));

            if (mode == 0) {
                if (t == (p ? e1 : e0)) {
                    float2 v; v.x = h0; v.y = h1;
                    *(float2*)(g_hf + (size_t)row*LL + colg) = v;
                }
            } else {
                float2 v; v.x = h0; v.y = h1;
                *(float2*)(decout + ((size_t)t*NB + row)*LL + colg) = v;
            }
        }

        // ---- grid barrier (skip after last step) ----
        if (t + 1 < T) {
            __threadfence();
            __syncthreads();
            if (tid == 0) {
                atomicAdd(&g_barrier, 1u);
                unsigned target = (unsigned)(RCTAS*(t + 1));
                unsigned v;
                do {
                    asm volatile("ld.global.cg.u32 %0, [%1];" : "=r"(v) : "l"(&g_barrier));
                } while (v < target);
                __threadfence();
            }
            __syncthreads();
        }
    }
}

__global__ void k_zero_barrier() { if (threadIdx.x == 0) g_barrier = 0u; }

// ---------------- fp32 TN GEMM (projection / heads) ----------------
#define BM 128
#define BN 64
#define BK 16
#define TM 8
#define TN 4

__global__ __launch_bounds__(256)
void gemm_tn(const float* __restrict__ A, const float* __restrict__ B,
             float* __restrict__ C, int M, int N, int K,
             int lda, int ldb, int klen)
{
    __shared__ float As[BK][BM+1];
    __shared__ float Bs[BK][BN+1];
    int tid = threadIdx.x;
    int m0 = blockIdx.y * BM;
    int n0 = blockIdx.x * BN;
    int k0 = blockIdx.z * klen;
    int kend = k0 + klen; if (kend > K) kend = K;
    int tx = tid & 15, ty = tid >> 4;

    float acc[TM][TN];
    #pragma unroll
    for (int i = 0; i < TM; i++)
        #pragma unroll
        for (int j = 0; j < TN; j++) acc[i][j] = 0.f;

    for (int kb = k0; kb < kend; kb += BK) {
        #pragma unroll
        for (int r = 0; r < (BK*BM)/256; r++) {
            int e = r*256 + tid;
            int kk = e & (BK-1);
            int mm = e >> 4;
            As[kk][mm] = A[(size_t)(m0+mm)*lda + kb + kk];
        }
        #pragma unroll
        for (int r = 0; r < (BK*BN)/256; r++) {
            int e = r*256 + tid;
            int kk = e & (BK-1);
            int nn = e >> 4;
            Bs[kk][nn] = B[(size_t)(n0+nn)*ldb + kb + kk];
        }
        __syncthreads();
        #pragma unroll
        for (int kk = 0; kk < BK; kk++) {
            float ra[TM], rb[TN];
            #pragma unroll
            for (int i = 0; i < TM; i++) ra[i] = As[kk][ty*TM+i];
            #pragma unroll
            for (int j = 0; j < TN; j++) rb[j] = Bs[kk][tx*TN+j];
            #pragma unroll
            for (int i = 0; i < TM; i++)
                #pragma unroll
                for (int j = 0; j < TN; j++)
                    acc[i][j] = fmaf(ra[i], rb[j], acc[i][j]);
        }
        __syncthreads();
    }
    float* Cz = C + (size_t)blockIdx.z * M * N;
    #pragma unroll
    for (int i = 0; i < TM; i++) {
        int m = m0 + ty*TM + i;
        #pragma unroll
        for (int j = 0; j < TN; j++)
            Cz[(size_t)m*N + n0 + tx*TN + j] = acc[i][j];
    }
}

// ---------------- small kernels ----------------
__global__ void k_prep(const float* __restrict__ s)
{
    int n = threadIdx.x;
    if (n >= NB) return;
    int end = 0;
    for (int t = 1; t < TT; t++) {
        const float* p = s + ((size_t)n*TT + t)*SS;
        bool allz = true;
        for (int k = 0; k < SS; k++) { if (p[k] != 0.f) { allz = false; break; } }
        if (allz) { end = t - 1; break; }
    }
    g_end[n] = end;
    g_start[n] = end + 2;
}

__global__ void k_seed_ones()
{
    int idx = blockIdx.x*blockDim.x + threadIdx.x;
    if (idx < NB*512) { g_hhi[0][idx] = 0x3F803F80u; g_hlo[0][idx] = 0u; }
}

__global__ void k_seed_emb()
{
    int idx = blockIdx.x*blockDim.x + threadIdx.x;
    if (idx >= NB*512) return;
    float2 e = ((const float2*)g_emb)[idx];
    unsigned hi = packbf(e.x, e.y);
    g_hhi[0][idx] = hi;
    g_hlo[0][idx] = packbf(e.x - bflo(hi), e.y - bfhi(hi));
}

__global__ void k_gather_enc(const float* __restrict__ s, const float* __restrict__ a)
{
    int idx = blockIdx.x*blockDim.x + threadIdx.x;
    if (idx >= TENC*NB*160) return;
    int k = idx % 160;
    int n = (idx/160) % NB;
    int t = idx / (160*NB);
    g_xbuf[idx] = (k < SS) ? s[((size_t)n*TT+t)*SS + k]
                           : a[((size_t)n*TT+t)*AAd + (k-SS)];
}

__global__ void k_gather_dec(const float* __restrict__ a)
{
    int idx = blockIdx.x*blockDim.x + threadIdx.x;
    if (idx >= TDEC*NB*AAd) return;
    int k = idx % AAd;
    int n = (idx/AAd) % NB;
    int t = idx / (AAd*NB);
    int src = (t + g_start[n]) % TT;
    g_abuf[idx] = a[((size_t)n*TT+src)*AAd + k];
}

__global__ void k_emb(const float* __restrict__ mu_b, const float* __restrict__ lv_b,
                      const float* __restrict__ eps)
{
    int idx = blockIdx.x*blockDim.x + threadIdx.x;
    if (idx >= NB*LL) return;
    int z = idx & 1023;
    float mu = mu_b[z], lv = lv_b[z];
    #pragma unroll
    for (int ks = 0; ks < 4; ks++) {
        mu += g_muparts[(size_t)ks*NB*LL + idx];
        lv += g_lvparts[(size_t)ks*NB*LL + idx];
    }
    g_emb[idx] = mu + expf(0.5f*lv)*eps[idx];
}

__global__ void k_relu_bias(float* __restrict__ y, const float* __restrict__ b,
                            int ncol, int total)
{
    int idx = blockIdx.x*blockDim.x + threadIdx.x;
    if (idx < total) y[idx] = fmaxf(y[idx] + b[idx % ncol], 0.f);
}

__global__ void k_loss(const float* __restrict__ d3b, const float* __restrict__ s_next)
{
    int bid = blockIdx.x;
    int t = bid >> 7, n = bid & 127;
    int st = g_start[n];
    int j = threadIdx.x;
    float v = 0.f;
    if (t < TT - st) {
        float pred = g_shat[(size_t)bid*SS + j] + d3b[j];
        int src = (t + st) % TT;
        v = fabsf(s_next[((size_t)n*TT+src)*SS + j] - pred);
    }
    __shared__ float sm[128];
    sm[j] = v; __syncthreads();
    for (int s2 = 64; s2 > 0; s2 >>= 1) {
        if (j < s2) sm[j] += sm[j+s2];
        __syncthreads();
    }
    if (j == 0) g_part[bid] = sm[0];
}

__global__ void k_reduce(float* __restrict__ out)
{
    __shared__ float sm[256];
    float acc = 0.f;
    for (int i = threadIdx.x; i < MDEC; i += 256) acc += g_part[i];
    sm[threadIdx.x] = acc; __syncthreads();
    for (int s2 = 128; s2 > 0; s2 >>= 1) {
        if (threadIdx.x < s2) sm[threadIdx.x] += sm[threadIdx.x+s2];
        __syncthreads();
    }
    if (threadIdx.x == 0) out[0] = sm[0];
}

// ---------------- host orchestration ----------------
extern "C" void kernel_launch(void* const* d_in, const int* in_sizes, int n_in,
                              void* d_out, int out_size)
{
    const float* s       = (const float*)d_in[0];
    const float* a       = (const float*)d_in[1];
    const float* s_next  = (const float*)d_in[3];
    const float* eps     = (const float*)d_in[4];
    const float* enc_Wih = (const float*)d_in[5];
    const float* enc_Whh = (const float*)d_in[6];
    const float* enc_bih = (const float*)d_in[7];
    const float* enc_bhh = (const float*)d_in[8];
    const float* mu_W    = (const float*)d_in[9];
    const float* mu_b    = (const float*)d_in[10];
    const float* lv_W    = (const float*)d_in[11];
    const float* lv_b    = (const float*)d_in[12];
    const float* dec_Wih = (const float*)d_in[19];
    const float* dec_Whh = (const float*)d_in[20];
    const float* dec_bih = (const float*)d_in[21];
    const float* dec_bhh = (const float*)d_in[22];
    const float* d1_W    = (const float*)d_in[23];
    const float* d1_b    = (const float*)d_in[24];
    const float* d2_W    = (const float*)d_in[25];
    const float* d2_b    = (const float*)d_in[26];
    const float* d3_W    = (const float*)d_in[27];
    const float* d3_b    = (const float*)d_in[28];

    float *xbuf, *xg_enc, *abuf, *xg_dec, *hf;
    float *muparts, *lvparts, *emb, *decout, *y1, *y2, *shat;
    cudaGetSymbolAddress((void**)&xbuf,    g_xbuf);
    cudaGetSymbolAddress((void**)&xg_enc,  g_xg_enc);
    cudaGetSymbolAddress((void**)&abuf,    g_abuf);
    cudaGetSymbolAddress((void**)&xg_dec,  g_xg_dec);
    cudaGetSymbolAddress((void**)&hf,      g_hf);
    cudaGetSymbolAddress((void**)&muparts, g_muparts);
    cudaGetSymbolAddress((void**)&lvparts, g_lvparts);
    cudaGetSymbolAddress((void**)&emb,     g_emb);
    cudaGetSymbolAddress((void**)&decout,  g_decout);
    cudaGetSymbolAddress((void**)&y1,      g_y1);
    cudaGetSymbolAddress((void**)&y2,      g_y2);
    cudaGetSymbolAddress((void**)&shat,    g_shat);

    cudaFuncSetAttribute(gru_persist, cudaFuncAttributeMaxDynamicSharedMemorySize,
                         SMEM2);

    // split points + encoder init
    k_prep<<<1, 128>>>(s);
    k_seed_ones<<<(NB*512 + 255)/256, 256>>>();

    // encoder input projection for all timesteps (parallel)
    k_gather_enc<<<(TENC*NB*160 + 255)/256, 256>>>(s, a);
    gemm_tn<<<dim3(GG/BN, TENC, 1), 256>>>(xbuf, enc_Wih, xg_enc,
                                           TENC*NB, GG, 160, 160, 160, 160);

    // encoder recurrence: ONE persistent launch, 98 steps
    k_zero_barrier<<<1, 32>>>();
    gru_persist<<<RCTAS, 256, SMEM2>>>(enc_Whh, xg_enc, enc_bih, enc_bhh,
                                       TENC, 0, nullptr);

    // reparametrize
    gemm_tn<<<dim3(LL/BN, 1, 4), 256>>>(hf, mu_W, muparts, NB, LL, LL, LL, LL, LL/4);
    gemm_tn<<<dim3(LL/BN, 1, 4), 256>>>(hf, lv_W, lvparts, NB, LL, LL, LL, LL, LL/4);
    k_emb<<<(NB*LL + 255)/256, 256>>>(mu_b, lv_b, eps);
    k_seed_emb<<<(NB*512 + 255)/256, 256>>>();

    // decoder input projection (rolled actions)
    k_gather_dec<<<(TDEC*NB*AAd + 255)/256, 256>>>(a);
    gemm_tn<<<dim3(GG/BN, TDEC, 1), 256>>>(abuf, dec_Wih, xg_dec,
                                           MDEC, GG, AAd, AAd, AAd, AAd);

    // decoder recurrence: ONE persistent launch, 49 steps
    k_zero_barrier<<<1, 32>>>();
    gru_persist<<<RCTAS, 256, SMEM2>>>(dec_Whh, xg_dec, dec_bih, dec_bhh,
                                       TDEC, 1, decout);

    // decoder MLP head
    gemm_tn<<<dim3(128/BN, MDEC/BM, 1), 256>>>(decout, d1_W, y1,
                                               MDEC, 128, LL, LL, LL, LL);
    k_relu_bias<<<(MDEC*128 + 255)/256, 256>>>(y1, d1_b, 128, MDEC*128);
    gemm_tn<<<dim3(64/BN, MDEC/BM, 1), 256>>>(y1, d2_W, y2,
                                              MDEC, 64, 128, 128, 128, 128);
    k_relu_bias<<<(MDEC*64 + 255)/256, 256>>>(y2, d2_b, 64, MDEC*64);
    gemm_tn<<<dim3(128/BN, MDEC/BM, 1), 256>>>(y2, d3_W, shat,
                                               MDEC, 128, 64, 64, 64, 64);

    // masked L1 loss, deterministic two-stage reduction
    k_loss<<<MDEC, 128>>>(d3_b, s_next);
    k_reduce<<<1, 256>>>((float*)d_out);
}

// round 6
// speedup vs baseline: 2.2072x; 1.1356x over previous
#include <cuda_runtime.h>
#include <math.h>
#include <stdint.h>

// ---------------- problem constants ----------------
#define NB   128
#define TT   100
#define SS   128
#define AAd  32
#define LL   1024
#define GG   3072
#define TENC 98
#define TDEC 49
#define MDEC (TDEC*NB)

// recurrence kernel geometry
#define RCTAS  128
#define HPC    8
#define NT     3
#define KS     64
#define CHUNKS 16
#define APITCH 36
#define APLANE (128*APITCH)
#define ABUF   (2*APLANE)
#define SW_U32 (KS*NT*32*4)
#define SA_OFF (SW_U32 + 64)
#define SMEM2  ((SA_OFF + 3*ABUF)*4)

// ---------------- device scratch ----------------
__device__ float    g_xbuf  [TENC*NB*160];
__device__ float    g_xg_enc[TENC*(size_t)NB*GG];
__device__ float    g_abuf  [TDEC*NB*AAd];
__device__ float    g_xg_dec[TDEC*(size_t)NB*GG];
__device__ unsigned g_hhi   [2][NB*512];
__device__ unsigned g_hlo   [2][NB*512];
__device__ float    g_hf    [NB*LL];
__device__ float    g_muparts[4*NB*LL];
__device__ float    g_lvparts[4*NB*LL];
__device__ float    g_emb   [NB*LL];
__device__ float    g_decout[TDEC*(size_t)NB*LL];
__device__ float    g_y1    [MDEC*128];
__device__ float    g_y2    [MDEC*64];
__device__ float    g_shat  [MDEC*128];
__device__ float    g_part  [MDEC];
__device__ int      g_end   [NB];
__device__ int      g_start [NB];
__device__ unsigned g_barrier;

// ---------------- bf16 bit helpers ----------------
__device__ __forceinline__ unsigned f2bf(float x) {
    unsigned u = __float_as_uint(x);
    return (u + 0x7FFFu + ((u >> 16) & 1u)) >> 16;
}
__device__ __forceinline__ unsigned packbf(float x, float y) {
    return f2bf(x) | (f2bf(y) << 16);
}
__device__ __forceinline__ float bflo(unsigned p) { return __uint_as_float(p << 16); }
__device__ __forceinline__ float bfhi(unsigned p) { return __uint_as_float(p & 0xFFFF0000u); }

__device__ __forceinline__ void mma16816(float* c, const uint32_t* a,
                                         uint32_t b0, uint32_t b1) {
    asm volatile(
        "mma.sync.aligned.m16n8k16.row.col.f32.bf16.bf16.f32 "
        "{%0,%1,%2,%3}, {%4,%5,%6,%7}, {%8,%9}, {%0,%1,%2,%3};"
        : "+f"(c[0]), "+f"(c[1]), "+f"(c[2]), "+f"(c[3])
        : "r"(a[0]), "r"(a[1]), "r"(a[2]), "r"(a[3]), "r"(b0), "r"(b1));
}
#define LDMX4(a, addr) asm volatile(                                        \
    "ldmatrix.sync.aligned.m8n8.x4.shared.b16 {%0,%1,%2,%3}, [%4];"         \
    : "=r"((a)[0]), "=r"((a)[1]), "=r"((a)[2]), "=r"((a)[3]) : "r"(addr))

__device__ __forceinline__ uint32_t smem_u32(const void* p) {
    uint32_t a;
    asm("{ .reg .u64 t; cvta.to.shared.u64 t, %1; cvt.u32.u64 %0, t; }"
        : "=r"(a) : "l"(p));
    return a;
}
__device__ __forceinline__ void cp16(uint32_t s, const void* g) {
    asm volatile("cp.async.cg.shared.global [%0], [%1], 16;" :: "r"(s), "l"(g));
}
__device__ __forceinline__ void cp_commit() { asm volatile("cp.async.commit_group;"); }
template<int N> __device__ __forceinline__ void cp_wait() {
    asm volatile("cp.async.wait_group %0;" :: "n"(N));
}

__device__ __forceinline__ float sigmf_(float x) { return 1.f / (1.f + __expf(-x)); }
__device__ __forceinline__ float tanhf_(float x) {
    float e = __expf(2.f * fabsf(x));
    return copysignf(1.f - 2.f / (e + 1.f), x);
}

// stage one 64-k-col chunk (both planes) into smem buffer via cp.async
__device__ __forceinline__ void stage_chunk(uint32_t sbuf, const unsigned* hiP,
                                            const unsigned* loP, int c, int tid)
{
    #pragma unroll
    for (int r = 0; r < 4; r++) {
        int j = tid + r*256;
        int row = j >> 3, seg = j & 7;
        uint32_t so = sbuf + row*144 + seg*16;
        const char* gh = (const char*)hiP + row*2048 + c*128 + seg*16;
        const char* gl = (const char*)loP + row*2048 + c*128 + seg*16;
        cp16(so, gh);
        cp16(so + APLANE*4, gl);
    }
    cp_commit();
}

// ============ persistent GRU recurrence ============
__global__ __launch_bounds__(256, 1)
void gru_persist(const float* __restrict__ Whh,
                 const float* __restrict__ xg_all,
                 const float* __restrict__ bih,
                 const float* __restrict__ bhh,
                 int T, int mode, float* __restrict__ decout)
{
    extern __shared__ unsigned dyn[];
    unsigned* sW = dyn;
    float* sb = (float*)(dyn + SW_U32);
    uint32_t sA0 = smem_u32(dyn + SA_OFF);

    int tid = threadIdx.x;
    int hc0 = blockIdx.x * HPC;

    // one-time weight pack
    for (int idx = tid; idx < KS*NT*32; idx += 256) {
        int lane = idx & 31;
        int nt   = (idx >> 5) % NT;
        int ks   = idx / (NT*32);
        int t4   = lane & 3;
        int grow = nt*1024 + hc0 + (lane >> 2);
        const float* wr = Whh + (size_t)grow*LL + ks*16 + 2*t4;
        float w0 = wr[0], w1 = wr[1], w2 = wr[8], w3 = wr[9];
        unsigned bh0 = packbf(w0, w1), bh1 = packbf(w2, w3);
        unsigned* d = sW + (size_t)idx*4;
        d[0] = bh0; d[1] = bh1;
        d[2] = packbf(w0 - bflo(bh0), w1 - bfhi(bh0));
        d[3] = packbf(w2 - bflo(bh1), w3 - bfhi(bh1));
    }
    if (tid < 6*HPC) {
        int gate = tid / HPC, j = tid % HPC;
        const float* src = (gate < 3) ? bih : bhh;
        sb[tid] = src[(gate % 3)*1024 + hc0 + j];
    }
    __syncthreads();

    int w = tid >> 5, lane = tid & 31;
    int g = lane >> 2, t4 = lane & 3;
    int r0 = w*16 + g, r1 = r0 + 8;
    int e0 = -1, e1 = -1;
    if (mode == 0) { e0 = g_end[r0]; e1 = g_end[r1]; }

    int jb = 2*t4;
    int colg = hc0 + jb;
    int pidx = colg >> 1;

    int m2 = lane >> 3, r8 = lane & 7;
    uint32_t ldm_off = (uint32_t)((w*16 + ((m2 & 1) << 3) + r8)*144 + (m2 >> 1)*16);

    float hprev[4];
    {
        unsigned p0 = g_hhi[0][r0*512 + pidx], q0 = g_hlo[0][r0*512 + pidx];
        unsigned p1 = g_hhi[0][r1*512 + pidx], q1 = g_hlo[0][r1*512 + pidx];
        hprev[0] = bflo(p0) + bflo(q0); hprev[1] = bfhi(p0) + bfhi(q0);
        hprev[2] = bflo(p1) + bflo(q1); hprev[3] = bfhi(p1) + bfhi(q1);
    }

    #pragma unroll 1
    for (int t = 0; t < T; t++) {
        int rb = t & 1;
        const unsigned* hiP = g_hhi[rb];
        const unsigned* loP = g_hlo[rb];
        unsigned* whiP = g_hhi[rb ^ 1];
        unsigned* wloP = g_hlo[rb ^ 1];

        // hoisted xg loads: overlap their latency with the whole mma loop
        const float* xg = xg_all + (size_t)t*NB*GG;
        float2 xr0 = *(const float2*)(xg + (size_t)r0*GG + colg);
        float2 xz0 = *(const float2*)(xg + (size_t)r0*GG + 1024 + colg);
        float2 xn0 = *(const float2*)(xg + (size_t)r0*GG + 2048 + colg);
        float2 xr1 = *(const float2*)(xg + (size_t)r1*GG + colg);
        float2 xz1 = *(const float2*)(xg + (size_t)r1*GG + 1024 + colg);
        float2 xn1 = *(const float2*)(xg + (size_t)r1*GG + 2048 + colg);

        float acc[NT][4];
        #pragma unroll
        for (int n = 0; n < NT; n++)
            #pragma unroll
            for (int c = 0; c < 4; c++) acc[n][c] = 0.f;

        stage_chunk(sA0,          hiP, loP, 0, tid);
        stage_chunk(sA0 + ABUF*4, hiP, loP, 1, tid);

        #pragma unroll 1
        for (int c = 0; c < CHUNKS; c++) {
            if (c + 1 < CHUNKS) { cp_wait<1>(); } else { cp_wait<0>(); }
            __syncthreads();
            if (c + 2 < CHUNKS)
                stage_chunk(sA0 + (uint32_t)((c + 2) % 3)*ABUF*4, hiP, loP, c + 2, tid);

            uint32_t hb = sA0 + (uint32_t)(c % 3)*ABUF*4 + ldm_off;
            #pragma unroll
            for (int ksl = 0; ksl < 4; ksl++) {
                uint32_t ahi[4], alo[4];
                uint32_t ad = hb + ksl*32;
                LDMX4(ahi, ad);
                LDMX4(alo, ad + APLANE*4);
                int ksg = c*4 + ksl;
                #pragma unroll
                for (int nt = 0; nt < NT; nt++) {
                    uint4 b = *(const uint4*)(sW + (size_t)((ksg*NT + nt)*32 + lane)*4);
                    mma16816(acc[nt], ahi, b.x, b.y);
                    mma16816(acc[nt], alo, b.x, b.y);
                    mma16816(acc[nt], ahi, b.z, b.w);
                }
            }
        }

        // fused GRU pointwise
        {
            float rr0 = sigmf_(xr0.x + sb[jb]      + acc[0][0] + sb[24+jb]);
            float rr1 = sigmf_(xr0.y + sb[jb+1]    + acc[0][1] + sb[24+jb+1]);
            float zz0 = sigmf_(xz0.x + sb[8+jb]    + acc[1][0] + sb[32+jb]);
            float zz1 = sigmf_(xz0.y + sb[8+jb+1]  + acc[1][1] + sb[32+jb+1]);
            float nn0 = tanhf_(xn0.x + sb[16+jb]   + rr0*(acc[2][0] + sb[40+jb]));
            float nn1 = tanhf_(xn0.y + sb[16+jb+1] + rr1*(acc[2][1] + sb[40+jb+1]));
            float h0 = (1.f - zz0)*nn0 + zz0*hprev[0];
            float h1 = (1.f - zz1)*nn1 + zz1*hprev[1];
            hprev[0] = h0; hprev[1] = h1;
            unsigned hiw = packbf(h0, h1);
            whiP[r0*512 + pidx] = hiw;
            wloP[r0*512 + pidx] = packbf(h0 - bflo(hiw), h1 - bfhi(hiw));
            if (mode == 0) {
                if (t == e0) { float2 v{h0, h1};
                    *(float2*)(g_hf + (size_t)r0*LL + colg) = v; }
            } else {
                float2 v{h0, h1};
                *(float2*)(decout + ((size_t)t*NB + r0)*LL + colg) = v;
            }
        }
        {
            float rr0 = sigmf_(xr1.x + sb[jb]      + acc[0][2] + sb[24+jb]);
            float rr1 = sigmf_(xr1.y + sb[jb+1]    + acc[0][3] + sb[24+jb+1]);
            float zz0 = sigmf_(xz1.x + sb[8+jb]    + acc[1][2] + sb[32+jb]);
            float zz1 = sigmf_(xz1.y + sb[8+jb+1]  + acc[1][3] + sb[32+jb+1]);
            float nn0 = tanhf_(xn1.x + sb[16+jb]   + rr0*(acc[2][2] + sb[40+jb]));
            float nn1 = tanhf_(xn1.y + sb[16+jb+1] + rr1*(acc[2][3] + sb[40+jb+1]));
            float h0 = (1.f - zz0)*nn0 + zz0*hprev[2];
            float h1 = (1.f - zz1)*nn1 + zz1*hprev[3];
            hprev[2] = h0; hprev[3] = h1;
            unsigned hiw = packbf(h0, h1);
            whiP[r1*512 + pidx] = hiw;
            wloP[r1*512 + pidx] = packbf(h0 - bflo(hiw), h1 - bfhi(hiw));
            if (mode == 0) {
                if (t == e1) { float2 v{h0, h1};
                    *(float2*)(g_hf + (size_t)r1*LL + colg) = v; }
            } else {
                float2 v{h0, h1};
                *(float2*)(decout + ((size_t)t*NB + r1)*LL + colg) = v;
            }
        }

        if (t + 1 < T) {
            __threadfence();
            __syncthreads();
            if (tid == 0) {
                atomicAdd(&g_barrier, 1u);
                unsigned target = (unsigned)(RCTAS*(t + 1));
                unsigned v;
                do {
                    asm volatile("ld.global.cg.u32 %0, [%1];" : "=r"(v) : "l"(&g_barrier));
                } while (v < target);
                __threadfence();
            }
            __syncthreads();
        }
    }
}

__global__ void k_zero_barrier() { if (threadIdx.x == 0) g_barrier = 0u; }

// ============ bf16 3-term mma GEMM: C[m,n] = sum_k A[m,k]*B[n,k] ============
// tiles 128x64x32; grid (N/64, M/128, zsplit); optional fused bias+relu.
__global__ __launch_bounds__(256)
void gemm_mma(const float* __restrict__ A, const float* __restrict__ B,
              float* __restrict__ C, int M, int N, int K, int lda, int ldb,
              int klen, const float* __restrict__ bias, int relu)
{
    __shared__ unsigned sA[128*36];
    __shared__ unsigned sB[64*36];
    int tid = threadIdx.x, lane = tid & 31, w = tid >> 5;
    int wm = w & 3, wn = w >> 2;
    int m0 = blockIdx.y*128, n0 = blockIdx.x*64;
    int k0 = blockIdx.z*klen;
    int kend = k0 + klen; if (kend > K) kend = K;
    uint32_t sAb = smem_u32(sA), sBb = smem_u32(sB);
    int m2 = lane >> 3, r8 = lane & 7;
    uint32_t frag_off = (uint32_t)((((m2 & 1) << 3) + r8)*144 + (m2 >> 1)*16);

    float acc[2][4][4];
    #pragma unroll
    for (int mt = 0; mt < 2; mt++)
        #pragma unroll
        for (int nt = 0; nt < 4; nt++)
            #pragma unroll
            for (int i = 0; i < 4; i++) acc[mt][nt][i] = 0.f;

    for (int kb = k0; kb < kend; kb += 32) {
        #pragma unroll
        for (int r = 0; r < 4; r++) {
            int idx = tid + r*256;
            int row = idx >> 3, c4 = idx & 7;
            float4 v = *(const float4*)(A + (size_t)(m0+row)*lda + kb + c4*4);
            unsigned h0 = packbf(v.x, v.y), h1 = packbf(v.z, v.w);
            unsigned* d = sA + row*36 + c4*2;
            d[0] = h0; d[1] = h1;
            d[16] = packbf(v.x - bflo(h0), v.y - bfhi(h0));
            d[17] = packbf(v.z - bflo(h1), v.w - bfhi(h1));
        }
        #pragma unroll
        for (int r = 0; r < 2; r++) {
            int idx = tid + r*256;
            int row = idx >> 3, c4 = idx & 7;
            float4 v = *(const float4*)(B + (size_t)(n0+row)*ldb + kb + c4*4);
            unsigned h0 = packbf(v.x, v.y), h1 = packbf(v.z, v.w);
            unsigned* d = sB + row*36 + c4*2;
            d[0] = h0; d[1] = h1;
            d[16] = packbf(v.x - bflo(h0), v.y - bfhi(h0));
            d[17] = packbf(v.z - bflo(h1), v.w - bfhi(h1));
        }
        __syncthreads();
        #pragma unroll
        for (int kk = 0; kk < 2; kk++) {
            uint32_t ahi[2][4], alo[2][4], bhi[2][4], blo[2][4];
            #pragma unroll
            for (int mt = 0; mt < 2; mt++) {
                uint32_t ad = sAb + (uint32_t)((wm*32 + mt*16)*144 + kk*32) + frag_off;
                LDMX4(ahi[mt], ad);
                LDMX4(alo[mt], ad + 64);
            }
            #pragma unroll
            for (int nh = 0; nh < 2; nh++) {
                uint32_t bd = sBb + (uint32_t)((wn*32 + nh*16)*144 + kk*32) + frag_off;
                LDMX4(bhi[nh], bd);
                LDMX4(blo[nh], bd + 64);
            }
            #pragma unroll
            for (int mt = 0; mt < 2; mt++)
                #pragma unroll
                for (int nt = 0; nt < 4; nt++) {
                    int nh = nt >> 1, s = nt & 1;
                    mma16816(acc[mt][nt], ahi[mt], bhi[nh][s], bhi[nh][s+2]);
                    mma16816(acc[mt][nt], alo[mt], bhi[nh][s], bhi[nh][s+2]);
                    mma16816(acc[mt][nt], ahi[mt], blo[nh][s], blo[nh][s+2]);
                }
        }
        __syncthreads();
    }

    float* Cz = C + (size_t)blockIdx.z * M * N;
    int cr = lane >> 2, cc = (lane & 3)*2;
    #pragma unroll
    for (int mt = 0; mt < 2; mt++)
        #pragma unroll
        for (int nt = 0; nt < 4; nt++) {
            int gm = m0 + wm*32 + mt*16 + cr;
            int gn = n0 + wn*32 + nt*8 + cc;
            float b0 = 0.f, b1 = 0.f;
            if (bias) { b0 = bias[gn]; b1 = bias[gn+1]; }
            float v0 = acc[mt][nt][0] + b0, v1 = acc[mt][nt][1] + b1;
            float v2 = acc[mt][nt][2] + b0, v3 = acc[mt][nt][3] + b1;
            if (relu) {
                v0 = fmaxf(v0, 0.f); v1 = fmaxf(v1, 0.f);
                v2 = fmaxf(v2, 0.f); v3 = fmaxf(v3, 0.f);
            }
            float2 p0; p0.x = v0; p0.y = v1;
            float2 p1; p1.x = v2; p1.y = v3;
            *(float2*)(Cz + (size_t)gm*N + gn) = p0;
            *(float2*)(Cz + (size_t)(gm+8)*N + gn) = p1;
        }
}

// ---------------- small kernels ----------------
__global__ void k_prep(const float* __restrict__ s)
{
    int n = threadIdx.x;
    if (n >= NB) return;
    int end = 0;
    for (int t = 1; t < TT; t++) {
        const float* p = s + ((size_t)n*TT + t)*SS;
        bool allz = true;
        for (int k = 0; k < SS; k++) { if (p[k] != 0.f) { allz = false; break; } }
        if (allz) { end = t - 1; break; }
    }
    g_end[n] = end;
    g_start[n] = end + 2;
}

__global__ void k_seed_ones()
{
    int idx = blockIdx.x*blockDim.x + threadIdx.x;
    if (idx < NB*512) { g_hhi[0][idx] = 0x3F803F80u; g_hlo[0][idx] = 0u; }
}

__global__ void k_seed_emb()
{
    int idx = blockIdx.x*blockDim.x + threadIdx.x;
    if (idx >= NB*512) return;
    float2 e = ((const float2*)g_emb)[idx];
    unsigned hi = packbf(e.x, e.y);
    g_hhi[0][idx] = hi;
    g_hlo[0][idx] = packbf(e.x - bflo(hi), e.y - bfhi(hi));
}

__global__ void k_gather_enc(const float* __restrict__ s, const float* __restrict__ a)
{
    int idx = blockIdx.x*blockDim.x + threadIdx.x;
    if (idx >= TENC*NB*160) return;
    int k = idx % 160;
    int n = (idx/160) % NB;
    int t = idx / (160*NB);
    g_xbuf[idx] = (k < SS) ? s[((size_t)n*TT+t)*SS + k]
                           : a[((size_t)n*TT+t)*AAd + (k-SS)];
}

__global__ void k_gather_dec(const float* __restrict__ a)
{
    int idx = blockIdx.x*blockDim.x + threadIdx.x;
    if (idx >= TDEC*NB*AAd) return;
    int k = idx % AAd;
    int n = (idx/AAd) % NB;
    int t = idx / (AAd*NB);
    int src = (t + g_start[n]) % TT;
    g_abuf[idx] = a[((size_t)n*TT+src)*AAd + k];
}

__global__ void k_emb(const float* __restrict__ mu_b, const float* __restrict__ lv_b,
                      const float* __restrict__ eps)
{
    int idx = blockIdx.x*blockDim.x + threadIdx.x;
    if (idx >= NB*LL) return;
    int z = idx & 1023;
    float mu = mu_b[z], lv = lv_b[z];
    #pragma unroll
    for (int ks = 0; ks < 4; ks++) {
        mu += g_muparts[(size_t)ks*NB*LL + idx];
        lv += g_lvparts[(size_t)ks*NB*LL + idx];
    }
    g_emb[idx] = mu + expf(0.5f*lv)*eps[idx];
}

__global__ void k_loss(const float* __restrict__ s_next)
{
    int bid = blockIdx.x;
    int t = bid >> 7, n = bid & 127;
    int st = g_start[n];
    int j = threadIdx.x;
    float v = 0.f;
    if (t < TT - st) {
        float pred = g_shat[(size_t)bid*SS + j];
        int src = (t + st) % TT;
        v = fabsf(s_next[((size_t)n*TT+src)*SS + j] - pred);
    }
    __shared__ float sm[128];
    sm[j] = v; __syncthreads();
    for (int s2 = 64; s2 > 0; s2 >>= 1) {
        if (j < s2) sm[j] += sm[j+s2];
        __syncthreads();
    }
    if (j == 0) g_part[bid] = sm[0];
}

__global__ void k_reduce(float* __restrict__ out)
{
    __shared__ float sm[256];
    float acc = 0.f;
    for (int i = threadIdx.x; i < MDEC; i += 256) acc += g_part[i];
    sm[threadIdx.x] = acc; __syncthreads();
    for (int s2 = 128; s2 > 0; s2 >>= 1) {
        if (threadIdx.x < s2) sm[threadIdx.x] += sm[threadIdx.x+s2];
        __syncthreads();
    }
    if (threadIdx.x == 0) out[0] = sm[0];
}

// ---------------- host orchestration ----------------
extern "C" void kernel_launch(void* const* d_in, const int* in_sizes, int n_in,
                              void* d_out, int out_size)
{
    const float* s       = (const float*)d_in[0];
    const float* a       = (const float*)d_in[1];
    const float* s_next  = (const float*)d_in[3];
    const float* eps     = (const float*)d_in[4];
    const float* enc_Wih = (const float*)d_in[5];
    const float* enc_Whh = (const float*)d_in[6];
    const float* enc_bih = (const float*)d_in[7];
    const float* enc_bhh = (const float*)d_in[8];
    const float* mu_W    = (const float*)d_in[9];
    const float* mu_b    = (const float*)d_in[10];
    const float* lv_W    = (const float*)d_in[11];
    const float* lv_b    = (const float*)d_in[12];
    const float* dec_Wih = (const float*)d_in[19];
    const float* dec_Whh = (const float*)d_in[20];
    const float* dec_bih = (const float*)d_in[21];
    const float* dec_bhh = (const float*)d_in[22];
    const float* d1_W    = (const float*)d_in[23];
    const float* d1_b    = (const float*)d_in[24];
    const float* d2_W    = (const float*)d_in[25];
    const float* d2_b    = (const float*)d_in[26];
    const float* d3_W    = (const float*)d_in[27];
    const float* d3_b    = (const float*)d_in[28];

    float *xbuf, *xg_enc, *abuf, *xg_dec, *hf;
    float *muparts, *lvparts, *emb, *decout, *y1, *y2, *shat;
    cudaGetSymbolAddress((void**)&xbuf,    g_xbuf);
    cudaGetSymbolAddress((void**)&xg_enc,  g_xg_enc);
    cudaGetSymbolAddress((void**)&abuf,    g_abuf);
    cudaGetSymbolAddress((void**)&xg_dec,  g_xg_dec);
    cudaGetSymbolAddress((void**)&hf,      g_hf);
    cudaGetSymbolAddress((void**)&muparts, g_muparts);
    cudaGetSymbolAddress((void**)&lvparts, g_lvparts);
    cudaGetSymbolAddress((void**)&emb,     g_emb);
    cudaGetSymbolAddress((void**)&decout,  g_decout);
    cudaGetSymbolAddress((void**)&y1,      g_y1);
    cudaGetSymbolAddress((void**)&y2,      g_y2);
    cudaGetSymbolAddress((void**)&shat,    g_shat);

    cudaFuncSetAttribute(gru_persist, cudaFuncAttributeMaxDynamicSharedMemorySize,
                         SMEM2);

    // split points + encoder init
    k_prep<<<1, 128>>>(s);
    k_seed_ones<<<(NB*512 + 255)/256, 256>>>();

    // encoder input projection (tensorized)
    k_gather_enc<<<(TENC*NB*160 + 255)/256, 256>>>(s, a);
    gemm_mma<<<dim3(GG/64, TENC*NB/128, 1), 256>>>(xbuf, enc_Wih, xg_enc,
        TENC*NB, GG, 160, 160, 160, 160, nullptr, 0);

    // encoder recurrence
    k_zero_barrier<<<1, 32>>>();
    gru_persist<<<RCTAS, 256, SMEM2>>>(enc_Whh, xg_enc, enc_bih, enc_bhh,
                                       TENC, 0, nullptr);

    // reparametrize (z-split 4)
    gemm_mma<<<dim3(LL/64, 1, 4), 256>>>(hf, mu_W, muparts,
        NB, LL, LL, LL, LL, LL/4, nullptr, 0);
    gemm_mma<<<dim3(LL/64, 1, 4), 256>>>(hf, lv_W, lvparts,
        NB, LL, LL, LL, LL, LL/4, nullptr, 0);
    k_emb<<<(NB*LL + 255)/256, 256>>>(mu_b, lv_b, eps);
    k_seed_emb<<<(NB*512 + 255)/256, 256>>>();

    // decoder input projection (rolled actions)
    k_gather_dec<<<(TDEC*NB*AAd + 255)/256, 256>>>(a);
    gemm_mma<<<dim3(GG/64, MDEC/128, 1), 256>>>(abuf, dec_Wih, xg_dec,
        MDEC, GG, AAd, AAd, AAd, AAd, nullptr, 0);

    // decoder recurrence
    k_zero_barrier<<<1, 32>>>();
    gru_persist<<<RCTAS, 256, SMEM2>>>(dec_Whh, xg_dec, dec_bih, dec_bhh,
                                       TDEC, 1, decout);

    // decoder MLP head (fused bias+relu)
    gemm_mma<<<dim3(128/64, MDEC/128, 1), 256>>>(decout, d1_W, y1,
        MDEC, 128, LL, LL, LL, LL, d1_b, 1);
    gemm_mma<<<dim3(1, MDEC/128, 1), 256>>>(y1, d2_W, y2,
        MDEC, 64, 128, 128, 128, 128, d2_b, 1);
    gemm_mma<<<dim3(128/64, MDEC/128, 1), 256>>>(y2, d3_W, shat,
        MDEC, 128, 64, 64, 64, 64, d3_b, 0);

    // masked L1 loss, deterministic two-stage reduction
    k_loss<<<MDEC, 128>>>(s_next);
    k_reduce<<<1, 256>>>((float*)d_out);
}

// round 7
// speedup vs baseline: 2.4901x; 1.1281x over previous
#include <cuda_runtime.h>
#include <math.h>
#include <stdint.h>

// ---------------- problem constants ----------------
#define NB   128
#define TT   100
#define SS   128
#define AAd  32
#define LL   1024
#define GG   3072
#define TENC 98
#define TDEC 49
#define MDEC (TDEC*NB)

// recurrence kernel geometry
#define RCTAS  128
#define HPC    8
#define NT     3
#define KS     64
#define CHUNKS 16
#define APITCH 36
#define APLANE (128*APITCH)
#define ABUF   (2*APLANE)
#define SW_U32 (KS*NT*32*4)
#define SA_OFF (SW_U32 + 64)
#define SMEM2  ((SA_OFF + 3*ABUF)*4)

// ---------------- device scratch ----------------
__device__ float    g_xbuf  [TENC*NB*160];
__device__ float    g_xg_enc[TENC*(size_t)NB*GG];
__device__ float    g_abuf  [TDEC*NB*AAd];
__device__ float    g_xg_dec[TDEC*(size_t)NB*GG];
__device__ unsigned g_hhi   [2][NB*512];
__device__ unsigned g_hlo   [2][NB*512];
__device__ float    g_hf    [NB*LL];
__device__ float    g_muparts[4*NB*LL];
__device__ float    g_lvparts[4*NB*LL];
__device__ float    g_emb   [NB*LL];
__device__ float    g_decout[TDEC*(size_t)NB*LL];
__device__ float    g_y1    [MDEC*128];
__device__ float    g_y2    [MDEC*64];
__device__ float    g_shat  [MDEC*128];
__device__ float    g_part  [MDEC];
__device__ int      g_end   [NB];
__device__ int      g_start [NB];
__device__ int      g_perm_enc[NB];
__device__ int      g_esort_enc[NB];
__device__ int      g_perm_dec[NB];
__device__ int      g_esort_dec[NB];
__device__ unsigned g_barrier;

// ---------------- bf16 bit helpers ----------------
__device__ __forceinline__ unsigned f2bf(float x) {
    unsigned u = __float_as_uint(x);
    return (u + 0x7FFFu + ((u >> 16) & 1u)) >> 16;
}
__device__ __forceinline__ unsigned packbf(float x, float y) {
    return f2bf(x) | (f2bf(y) << 16);
}
__device__ __forceinline__ float bflo(unsigned p) { return __uint_as_float(p << 16); }
__device__ __forceinline__ float bfhi(unsigned p) { return __uint_as_float(p & 0xFFFF0000u); }

__device__ __forceinline__ void mma16816(float* c, const uint32_t* a,
                                         uint32_t b0, uint32_t b1) {
    asm volatile(
        "mma.sync.aligned.m16n8k16.row.col.f32.bf16.bf16.f32 "
        "{%0,%1,%2,%3}, {%4,%5,%6,%7}, {%8,%9}, {%0,%1,%2,%3};"
        : "+f"(c[0]), "+f"(c[1]), "+f"(c[2]), "+f"(c[3])
        : "r"(a[0]), "r"(a[1]), "r"(a[2]), "r"(a[3]), "r"(b0), "r"(b1));
}
#define LDMX4(a, addr) asm volatile(                                        \
    "ldmatrix.sync.aligned.m8n8.x4.shared.b16 {%0,%1,%2,%3}, [%4];"         \
    : "=r"((a)[0]), "=r"((a)[1]), "=r"((a)[2]), "=r"((a)[3]) : "r"(addr))

__device__ __forceinline__ uint32_t smem_u32(const void* p) {
    uint32_t a;
    asm("{ .reg .u64 t; cvta.to.shared.u64 t, %1; cvt.u32.u64 %0, t; }"
        : "=r"(a) : "l"(p));
    return a;
}
__device__ __forceinline__ void cp16(uint32_t s, const void* g) {
    asm volatile("cp.async.cg.shared.global [%0], [%1], 16;" :: "r"(s), "l"(g));
}
__device__ __forceinline__ void cp_commit() { asm volatile("cp.async.commit_group;"); }
template<int N> __device__ __forceinline__ void cp_wait() {
    asm volatile("cp.async.wait_group %0;" :: "n"(N));
}

__device__ __forceinline__ float sigmf_(float x) { return 1.f / (1.f + __expf(-x)); }
__device__ __forceinline__ float tanhf_(float x) {
    float e = __expf(2.f * fabsf(x));
    return copysignf(1.f - 2.f / (e + 1.f), x);
}

// stage one 64-k-col chunk (both planes), only the first rows16 rows
__device__ __forceinline__ void stage_chunk(uint32_t sbuf, const unsigned* hiP,
                                            const unsigned* loP, int c, int tid,
                                            int rows16)
{
    #pragma unroll
    for (int r = 0; r < 4; r++) {
        int j = tid + r*256;
        int row = j >> 3, seg = j & 7;
        if (row < rows16) {
            uint32_t so = sbuf + row*144 + seg*16;
            cp16(so, (const char*)hiP + row*2048 + c*128 + seg*16);
            cp16(so + APLANE*4, (const char*)loP + row*2048 + c*128 + seg*16);
        }
    }
    cp_commit();
}

// ============ persistent GRU recurrence (length-sorted early exit) ============
// Rows are in SORTED space; esorted[i] = last active step for sorted row i
// (descending). perm[i] = original batch index of sorted row i.
__global__ __launch_bounds__(256, 1)
void gru_persist(const float* __restrict__ Whh,
                 const float* __restrict__ xg_all,
                 const float* __restrict__ bih,
                 const float* __restrict__ bhh,
                 int T, int mode, float* __restrict__ decout,
                 const int* __restrict__ esorted, const int* __restrict__ perm)
{
    extern __shared__ unsigned dyn[];
    unsigned* sW = dyn;
    float* sb = (float*)(dyn + SW_U32);
    uint32_t sA0 = smem_u32(dyn + SA_OFF);
    __shared__ int sE[NB];
    __shared__ int sP[NB];

    int tid = threadIdx.x;
    int hc0 = blockIdx.x * HPC;

    if (tid < NB) { sE[tid] = esorted[tid]; sP[tid] = perm[tid]; }

    // one-time weight pack
    for (int idx = tid; idx < KS*NT*32; idx += 256) {
        int lane = idx & 31;
        int nt   = (idx >> 5) % NT;
        int ks   = idx / (NT*32);
        int t4   = lane & 3;
        int grow = nt*1024 + hc0 + (lane >> 2);
        const float* wr = Whh + (size_t)grow*LL + ks*16 + 2*t4;
        float w0 = wr[0], w1 = wr[1], w2 = wr[8], w3 = wr[9];
        unsigned bh0 = packbf(w0, w1), bh1 = packbf(w2, w3);
        unsigned* d = sW + (size_t)idx*4;
        d[0] = bh0; d[1] = bh1;
        d[2] = packbf(w0 - bflo(bh0), w1 - bfhi(bh0));
        d[3] = packbf(w2 - bflo(bh1), w3 - bfhi(bh1));
    }
    if (tid < 6*HPC) {
        int gate = tid / HPC, j = tid % HPC;
        const float* src = (gate < 3) ? bih : bhh;
        sb[tid] = src[(gate % 3)*1024 + hc0 + j];
    }
    __syncthreads();

    int w = tid >> 5, lane = tid & 31;
    int g = lane >> 2, t4 = lane & 3;
    int r0 = w*16 + g, r1 = r0 + 8;
    int e0 = sE[r0], e1 = sE[r1];
    int o0 = sP[r0], o1 = sP[r1];

    int jb = 2*t4;
    int colg = hc0 + jb;
    int pidx = colg >> 1;

    int m2 = lane >> 3, r8 = lane & 7;
    uint32_t ldm_off = (uint32_t)((w*16 + ((m2 & 1) << 3) + r8)*144 + (m2 >> 1)*16);

    float hprev[4];
    {
        unsigned p0 = g_hhi[0][r0*512 + pidx], q0 = g_hlo[0][r0*512 + pidx];
        unsigned p1 = g_hhi[0][r1*512 + pidx], q1 = g_hlo[0][r1*512 + pidx];
        hprev[0] = bflo(p0) + bflo(q0); hprev[1] = bfhi(p0) + bfhi(q0);
        hprev[2] = bflo(p1) + bflo(q1); hprev[3] = bfhi(p1) + bfhi(q1);
    }

    #pragma unroll 1
    for (int t = 0; t < T; t++) {
        // active 16-row groups at this step (prefix, since sorted descending)
        int m16 = 0;
        #pragma unroll
        for (int gg = 0; gg < 8; gg++) m16 += (sE[gg << 4] >= t) ? 1 : 0;

        if (m16 > 0) {
            int rows16 = m16 << 4;
            int rb = t & 1;
            const unsigned* hiP = g_hhi[rb];
            const unsigned* loP = g_hlo[rb];
            unsigned* whiP = g_hhi[rb ^ 1];
            unsigned* wloP = g_hlo[rb ^ 1];

            int a0 = (t <= e0), a1 = (t <= e1);
            const float* xg = xg_all + (size_t)t*NB*GG;
            float2 xr0{0,0}, xz0{0,0}, xn0{0,0}, xr1{0,0}, xz1{0,0}, xn1{0,0};
            if (a0) {
                xr0 = *(const float2*)(xg + (size_t)r0*GG + colg);
                xz0 = *(const float2*)(xg + (size_t)r0*GG + 1024 + colg);
                xn0 = *(const float2*)(xg + (size_t)r0*GG + 2048 + colg);
            }
            if (a1) {
                xr1 = *(const float2*)(xg + (size_t)r1*GG + colg);
                xz1 = *(const float2*)(xg + (size_t)r1*GG + 1024 + colg);
                xn1 = *(const float2*)(xg + (size_t)r1*GG + 2048 + colg);
            }

            float acc[NT][4];
            #pragma unroll
            for (int n = 0; n < NT; n++)
                #pragma unroll
                for (int c = 0; c < 4; c++) acc[n][c] = 0.f;

            stage_chunk(sA0,          hiP, loP, 0, tid, rows16);
            stage_chunk(sA0 + ABUF*4, hiP, loP, 1, tid, rows16);

            bool wact = (w < m16);
            #pragma unroll 1
            for (int c = 0; c < CHUNKS; c++) {
                if (c + 1 < CHUNKS) { cp_wait<1>(); } else { cp_wait<0>(); }
                __syncthreads();
                if (c + 2 < CHUNKS)
                    stage_chunk(sA0 + (uint32_t)((c + 2) % 3)*ABUF*4, hiP, loP,
                                c + 2, tid, rows16);

                if (wact) {
                    uint32_t hb = sA0 + (uint32_t)(c % 3)*ABUF*4 + ldm_off;
                    #pragma unroll
                    for (int ksl = 0; ksl < 4; ksl++) {
                        uint32_t ahi[4], alo[4];
                        uint32_t ad = hb + ksl*32;
                        LDMX4(ahi, ad);
                        LDMX4(alo, ad + APLANE*4);
                        int ksg = c*4 + ksl;
                        #pragma unroll
                        for (int nt = 0; nt < NT; nt++) {
                            uint4 b = *(const uint4*)(sW + (size_t)((ksg*NT + nt)*32 + lane)*4);
                            mma16816(acc[nt], ahi, b.x, b.y);
                            mma16816(acc[nt], alo, b.x, b.y);
                            mma16816(acc[nt], ahi, b.z, b.w);
                        }
                    }
                }
            }

            if (a0) {
                float rr0 = sigmf_(xr0.x + sb[jb]      + acc[0][0] + sb[24+jb]);
                float rr1 = sigmf_(xr0.y + sb[jb+1]    + acc[0][1] + sb[24+jb+1]);
                float zz0 = sigmf_(xz0.x + sb[8+jb]    + acc[1][0] + sb[32+jb]);
                float zz1 = sigmf_(xz0.y + sb[8+jb+1]  + acc[1][1] + sb[32+jb+1]);
                float nn0 = tanhf_(xn0.x + sb[16+jb]   + rr0*(acc[2][0] + sb[40+jb]));
                float nn1 = tanhf_(xn0.y + sb[16+jb+1] + rr1*(acc[2][1] + sb[40+jb+1]));
                float h0 = (1.f - zz0)*nn0 + zz0*hprev[0];
                float h1 = (1.f - zz1)*nn1 + zz1*hprev[1];
                hprev[0] = h0; hprev[1] = h1;
                unsigned hiw = packbf(h0, h1);
                whiP[r0*512 + pidx] = hiw;
                wloP[r0*512 + pidx] = packbf(h0 - bflo(hiw), h1 - bfhi(hiw));
                if (mode == 0) {
                    if (t == e0) { float2 v{h0, h1};
                        *(float2*)(g_hf + (size_t)o0*LL + colg) = v; }
                } else {
                    float2 v{h0, h1};
                    *(float2*)(decout + ((size_t)t*NB + o0)*LL + colg) = v;
                }
            }
            if (a1) {
                float rr0 = sigmf_(xr1.x + sb[jb]      + acc[0][2] + sb[24+jb]);
                float rr1 = sigmf_(xr1.y + sb[jb+1]    + acc[0][3] + sb[24+jb+1]);
                float zz0 = sigmf_(xz1.x + sb[8+jb]    + acc[1][2] + sb[32+jb]);
                float zz1 = sigmf_(xz1.y + sb[8+jb+1]  + acc[1][3] + sb[32+jb+1]);
                float nn0 = tanhf_(xn1.x + sb[16+jb]   + rr0*(acc[2][2] + sb[40+jb]));
                float nn1 = tanhf_(xn1.y + sb[16+jb+1] + rr1*(acc[2][3] + sb[40+jb+1]));
                float h0 = (1.f - zz0)*nn0 + zz0*hprev[2];
                float h1 = (1.f - zz1)*nn1 + zz1*hprev[3];
                hprev[2] = h0; hprev[3] = h1;
                unsigned hiw = packbf(h0, h1);
                whiP[r1*512 + pidx] = hiw;
                wloP[r1*512 + pidx] = packbf(h0 - bflo(hiw), h1 - bfhi(hiw));
                if (mode == 0) {
                    if (t == e1) { float2 v{h0, h1};
                        *(float2*)(g_hf + (size_t)o1*LL + colg) = v; }
                } else {
                    float2 v{h0, h1};
                    *(float2*)(decout + ((size_t)t*NB + o1)*LL + colg) = v;
                }
            }
        }

        if (t + 1 < T) {
            __threadfence();
            __syncthreads();
            if (tid == 0) {
                atomicAdd(&g_barrier, 1u);
                unsigned target = (unsigned)(RCTAS*(t + 1));
                unsigned v;
                do {
                    asm volatile("ld.global.cg.u32 %0, [%1];" : "=r"(v) : "l"(&g_barrier));
                } while (v < target);
                __threadfence();
            }
            __syncthreads();
        }
    }
}

__global__ void k_zero_barrier() { if (threadIdx.x == 0) g_barrier = 0u; }

// ============ bf16 3-term mma GEMM: C[m,n] = sum_k A[m,k]*B[n,k] ============
__global__ __launch_bounds__(256)
void gemm_mma(const float* __restrict__ A, const float* __restrict__ B,
              float* __restrict__ C, int M, int N, int K, int lda, int ldb,
              int klen, const float* __restrict__ bias, int relu)
{
    __shared__ unsigned sA[128*36];
    __shared__ unsigned sB[64*36];
    int tid = threadIdx.x, lane = tid & 31, w = tid >> 5;
    int wm = w & 3, wn = w >> 2;
    int m0 = blockIdx.y*128, n0 = blockIdx.x*64;
    int k0 = blockIdx.z*klen;
    int kend = k0 + klen; if (kend > K) kend = K;
    uint32_t sAb = smem_u32(sA), sBb = smem_u32(sB);
    int m2 = lane >> 3, r8 = lane & 7;
    uint32_t frag_off = (uint32_t)((((m2 & 1) << 3) + r8)*144 + (m2 >> 1)*16);

    float acc[2][4][4];
    #pragma unroll
    for (int mt = 0; mt < 2; mt++)
        #pragma unroll
        for (int nt = 0; nt < 4; nt++)
            #pragma unroll
            for (int i = 0; i < 4; i++) acc[mt][nt][i] = 0.f;

    for (int kb = k0; kb < kend; kb += 32) {
        #pragma unroll
        for (int r = 0; r < 4; r++) {
            int idx = tid + r*256;
            int row = idx >> 3, c4 = idx & 7;
            float4 v = *(const float4*)(A + (size_t)(m0+row)*lda + kb + c4*4);
            unsigned h0 = packbf(v.x, v.y), h1 = packbf(v.z, v.w);
            unsigned* d = sA + row*36 + c4*2;
            d[0] = h0; d[1] = h1;
            d[16] = packbf(v.x - bflo(h0), v.y - bfhi(h0));
            d[17] = packbf(v.z - bflo(h1), v.w - bfhi(h1));
        }
        #pragma unroll
        for (int r = 0; r < 2; r++) {
            int idx = tid + r*256;
            int row = idx >> 3, c4 = idx & 7;
            float4 v = *(const float4*)(B + (size_t)(n0+row)*ldb + kb + c4*4);
            unsigned h0 = packbf(v.x, v.y), h1 = packbf(v.z, v.w);
            unsigned* d = sB + row*36 + c4*2;
            d[0] = h0; d[1] = h1;
            d[16] = packbf(v.x - bflo(h0), v.y - bfhi(h0));
            d[17] = packbf(v.z - bflo(h1), v.w - bfhi(h1));
        }
        __syncthreads();
        #pragma unroll
        for (int kk = 0; kk < 2; kk++) {
            uint32_t ahi[2][4], alo[2][4], bhi[2][4], blo[2][4];
            #pragma unroll
            for (int mt = 0; mt < 2; mt++) {
                uint32_t ad = sAb + (uint32_t)((wm*32 + mt*16)*144 + kk*32) + frag_off;
                LDMX4(ahi[mt], ad);
                LDMX4(alo[mt], ad + 64);
            }
            #pragma unroll
            for (int nh = 0; nh < 2; nh++) {
                uint32_t bd = sBb + (uint32_t)((wn*32 + nh*16)*144 + kk*32) + frag_off;
                LDMX4(bhi[nh], bd);
                LDMX4(blo[nh], bd + 64);
            }
            #pragma unroll
            for (int mt = 0; mt < 2; mt++)
                #pragma unroll
                for (int nt = 0; nt < 4; nt++) {
                    int nh = nt >> 1, s = nt & 1;
                    mma16816(acc[mt][nt], ahi[mt], bhi[nh][s], bhi[nh][s+2]);
                    mma16816(acc[mt][nt], alo[mt], bhi[nh][s], bhi[nh][s+2]);
                    mma16816(acc[mt][nt], ahi[mt], blo[nh][s], blo[nh][s+2]);
                }
        }
        __syncthreads();
    }

    float* Cz = C + (size_t)blockIdx.z * M * N;
    int cr = lane >> 2, cc = (lane & 3)*2;
    #pragma unroll
    for (int mt = 0; mt < 2; mt++)
        #pragma unroll
        for (int nt = 0; nt < 4; nt++) {
            int gm = m0 + wm*32 + mt*16 + cr;
            int gn = n0 + wn*32 + nt*8 + cc;
            float b0 = 0.f, b1 = 0.f;
            if (bias) { b0 = bias[gn]; b1 = bias[gn+1]; }
            float v0 = acc[mt][nt][0] + b0, v1 = acc[mt][nt][1] + b1;
            float v2 = acc[mt][nt][2] + b0, v3 = acc[mt][nt][3] + b1;
            if (relu) {
                v0 = fmaxf(v0, 0.f); v1 = fmaxf(v1, 0.f);
                v2 = fmaxf(v2, 0.f); v3 = fmaxf(v3, 0.f);
            }
            float2 p0; p0.x = v0; p0.y = v1;
            float2 p1; p1.x = v2; p1.y = v3;
            *(float2*)(Cz + (size_t)gm*N + gn) = p0;
            *(float2*)(Cz + (size_t)(gm+8)*N + gn) = p1;
        }
}

// ---------------- small kernels ----------------
// split points + deterministic rank sort (enc: end desc; dec: end asc)
__global__ void k_prep(const float* __restrict__ s)
{
    __shared__ int sEnd[NB];
    int n = threadIdx.x;
    if (n >= NB) return;
    int end = 0;
    for (int t = 1; t < TT; t++) {
        const float* p = s + ((size_t)n*TT + t)*SS;
        bool allz = true;
        for (int k = 0; k < SS; k++) { if (p[k] != 0.f) { allz = false; break; } }
        if (allz) { end = t - 1; break; }
    }
    g_end[n] = end;
    g_start[n] = end + 2;
    sEnd[n] = end;
    __syncthreads();
    int r_enc = 0, r_dec = 0;
    for (int j = 0; j < NB; j++) {
        int ej = sEnd[j];
        r_enc += (ej > end) || (ej == end && j < n);
        r_dec += (ej < end) || (ej == end && j < n);
    }
    g_perm_enc[r_enc]  = n;  g_esort_enc[r_enc] = end;
    g_perm_dec[r_dec]  = n;  g_esort_dec[r_dec] = 97 - end;  // last needed dec step
}

__global__ void k_seed_ones()
{
    int idx = blockIdx.x*blockDim.x + threadIdx.x;
    if (idx < NB*512) { g_hhi[0][idx] = 0x3F803F80u; g_hlo[0][idx] = 0u; }
}

// decoder h0 = emb, permuted into dec-sorted order
__global__ void k_seed_emb()
{
    int idx = blockIdx.x*blockDim.x + threadIdx.x;
    if (idx >= NB*512) return;
    int row = idx >> 9;
    int orig = g_perm_dec[row];
    float2 e = ((const float2*)g_emb)[(size_t)orig*512 + (idx & 511)];
    unsigned hi = packbf(e.x, e.y);
    g_hhi[0][idx] = hi;
    g_hlo[0][idx] = packbf(e.x - bflo(hi), e.y - bfhi(hi));
}

// encoder input gather, permuted into enc-sorted order
__global__ void k_gather_enc(const float* __restrict__ s, const float* __restrict__ a)
{
    int idx = blockIdx.x*blockDim.x + threadIdx.x;
    if (idx >= TENC*NB*160) return;
    int k = idx % 160;
    int n = (idx/160) % NB;
    int t = idx / (160*NB);
    int orig = g_perm_enc[n];
    g_xbuf[idx] = (k < SS) ? s[((size_t)orig*TT+t)*SS + k]
                           : a[((size_t)orig*TT+t)*AAd + (k-SS)];
}

// decoder input gather (rolled actions), permuted into dec-sorted order
__global__ void k_gather_dec(const float* __restrict__ a)
{
    int idx = blockIdx.x*blockDim.x + threadIdx.x;
    if (idx >= TDEC*NB*AAd) return;
    int k = idx % AAd;
    int n = (idx/AAd) % NB;
    int t = idx / (AAd*NB);
    int orig = g_perm_dec[n];
    int src = (t + g_start[orig]) % TT;
    g_abuf[idx] = a[((size_t)orig*TT+src)*AAd + k];
}

__global__ void k_emb(const float* __restrict__ mu_b, const float* __restrict__ lv_b,
                      const float* __restrict__ eps)
{
    int idx = blockIdx.x*blockDim.x + threadIdx.x;
    if (idx >= NB*LL) return;
    int z = idx & 1023;
    float mu = mu_b[z], lv = lv_b[z];
    #pragma unroll
    for (int ks = 0; ks < 4; ks++) {
        mu += g_muparts[(size_t)ks*NB*LL + idx];
        lv += g_lvparts[(size_t)ks*NB*LL + idx];
    }
    g_emb[idx] = mu + expf(0.5f*lv)*eps[idx];
}

__global__ void k_loss(const float* __restrict__ s_next)
{
    int bid = blockIdx.x;
    int t = bid >> 7, n = bid & 127;
    int st = g_start[n];
    int j = threadIdx.x;
    float v = 0.f;
    if (t < TT - st) {
        float pred = g_shat[(size_t)bid*SS + j];
        int src = (t + st) % TT;
        v = fabsf(s_next[((size_t)n*TT+src)*SS + j] - pred);
    }
    __shared__ float sm[128];
    sm[j] = v; __syncthreads();
    for (int s2 = 64; s2 > 0; s2 >>= 1) {
        if (j < s2) sm[j] += sm[j+s2];
        __syncthreads();
    }
    if (j == 0) g_part[bid] = sm[0];
}

__global__ void k_reduce(float* __restrict__ out)
{
    __shared__ float sm[256];
    float acc = 0.f;
    for (int i = threadIdx.x; i < MDEC; i += 256) acc += g_part[i];
    sm[threadIdx.x] = acc; __syncthreads();
    for (int s2 = 128; s2 > 0; s2 >>= 1) {
        if (threadIdx.x < s2) sm[threadIdx.x] += sm[threadIdx.x+s2];
        __syncthreads();
    }
    if (threadIdx.x == 0) out[0] = sm[0];
}

// ---------------- host orchestration ----------------
extern "C" void kernel_launch(void* const* d_in, const int* in_sizes, int n_in,
                              void* d_out, int out_size)
{
    const float* s       = (const float*)d_in[0];
    const float* a       = (const float*)d_in[1];
    const float* s_next  = (const float*)d_in[3];
    const float* eps     = (const float*)d_in[4];
    const float* enc_Wih = (const float*)d_in[5];
    const float* enc_Whh = (const float*)d_in[6];
    const float* enc_bih = (const float*)d_in[7];
    const float* enc_bhh = (const float*)d_in[8];
    const float* mu_W    = (const float*)d_in[9];
    const float* mu_b    = (const float*)d_in[10];
    const float* lv_W    = (const float*)d_in[11];
    const float* lv_b    = (const float*)d_in[12];
    const float* dec_Wih = (const float*)d_in[19];
    const float* dec_Whh = (const float*)d_in[20];
    const float* dec_bih = (const float*)d_in[21];
    const float* dec_bhh = (const float*)d_in[22];
    const float* d1_W    = (const float*)d_in[23];
    const float* d1_b    = (const float*)d_in[24];
    const float* d2_W    = (const float*)d_in[25];
    const float* d2_b    = (const float*)d_in[26];
    const float* d3_W    = (const float*)d_in[27];
    const float* d3_b    = (const float*)d_in[28];

    float *xbuf, *xg_enc, *abuf, *xg_dec, *hf;
    float *muparts, *lvparts, *emb, *decout, *y1, *y2, *shat;
    int *pe, *ee, *pd, *ed;
    cudaGetSymbolAddress((void**)&xbuf,    g_xbuf);
    cudaGetSymbolAddress((void**)&xg_enc,  g_xg_enc);
    cudaGetSymbolAddress((void**)&abuf,    g_abuf);
    cudaGetSymbolAddress((void**)&xg_dec,  g_xg_dec);
    cudaGetSymbolAddress((void**)&hf,      g_hf);
    cudaGetSymbolAddress((void**)&muparts, g_muparts);
    cudaGetSymbolAddress((void**)&lvparts, g_lvparts);
    cudaGetSymbolAddress((void**)&emb,     g_emb);
    cudaGetSymbolAddress((void**)&decout,  g_decout);
    cudaGetSymbolAddress((void**)&y1,      g_y1);
    cudaGetSymbolAddress((void**)&y2,      g_y2);
    cudaGetSymbolAddress((void**)&shat,    g_shat);
    cudaGetSymbolAddress((void**)&pe,      g_perm_enc);
    cudaGetSymbolAddress((void**)&ee,      g_esort_enc);
    cudaGetSymbolAddress((void**)&pd,      g_perm_dec);
    cudaGetSymbolAddress((void**)&ed,      g_esort_dec);

    cudaFuncSetAttribute(gru_persist, cudaFuncAttributeMaxDynamicSharedMemorySize,
                         SMEM2);

    // split points + sort + encoder init
    k_prep<<<1, 128>>>(s);
    k_seed_ones<<<(NB*512 + 255)/256, 256>>>();

    // encoder input projection (tensorized, enc-sorted rows)
    k_gather_enc<<<(TENC*NB*160 + 255)/256, 256>>>(s, a);
    gemm_mma<<<dim3(GG/64, TENC*NB/128, 1), 256>>>(xbuf, enc_Wih, xg_enc,
        TENC*NB, GG, 160, 160, 160, 160, nullptr, 0);

    // encoder recurrence (early-exit by sorted length)
    k_zero_barrier<<<1, 32>>>();
    gru_persist<<<RCTAS, 256, SMEM2>>>(enc_Whh, xg_enc, enc_bih, enc_bhh,
                                       TENC, 0, nullptr, ee, pe);

    // reparametrize
    gemm_mma<<<dim3(LL/64, 1, 4), 256>>>(hf, mu_W, muparts,
        NB, LL, LL, LL, LL, LL/4, nullptr, 0);
    gemm_mma<<<dim3(LL/64, 1, 4), 256>>>(hf, lv_W, lvparts,
        NB, LL, LL, LL, LL, LL/4, nullptr, 0);
    k_emb<<<(NB*LL + 255)/256, 256>>>(mu_b, lv_b, eps);
    k_seed_emb<<<(NB*512 + 255)/256, 256>>>();

    // decoder input projection (dec-sorted rows)
    k_gather_dec<<<(TDEC*NB*AAd + 255)/256, 256>>>(a);
    gemm_mma<<<dim3(GG/64, MDEC/128, 1), 256>>>(abuf, dec_Wih, xg_dec,
        MDEC, GG, AAd, AAd, AAd, AAd, nullptr, 0);

    // decoder recurrence (early-exit; decout scattered to original rows)
    k_zero_barrier<<<1, 32>>>();
    gru_persist<<<RCTAS, 256, SMEM2>>>(dec_Whh, xg_dec, dec_bih, dec_bhh,
                                       TDEC, 1, decout, ed, pd);

    // decoder MLP head (fused bias+relu)
    gemm_mma<<<dim3(128/64, MDEC/128, 1), 256>>>(decout, d1_W, y1,
        MDEC, 128, LL, LL, LL, LL, d1_b, 1);
    gemm_mma<<<dim3(1, MDEC/128, 1), 256>>>(y1, d2_W, y2,
        MDEC, 64, 128, 128, 128, 128, d2_b, 1);
    gemm_mma<<<dim3(128/64, MDEC/128, 1), 256>>>(y2, d3_W, shat,
        MDEC, 128, 64, 64, 64, 64, d3_b, 0);

    // masked L1 loss, deterministic two-stage reduction
    k_loss<<<MDEC, 128>>>(s_next);
    k_reduce<<<1, 256>>>((float*)d_out);
}